// round 5
// baseline (speedup 1.0000x reference)
#include <cuda_runtime.h>
#include <math.h>
#include <float.h>
#include <stdint.h>

// Problem constants (fixed by setup_inputs)
#define Bc 16
#define Nc 21504           // 128^2 + 64^2 + 32^2 anchors
#define Mc 64
#define Cc 15
#define ABp 91             // angle bins + 1
#define BNc (Bc*Nc)        // 344064
#define NEGBLK (BNc/256)   // 1344
#define POSBLK 52          // 52*256 = 13312 >= max positives
#define CAND 768           // per-GT candidate cap (max in-box cells ~525)
#define EPSA 1e-9f
#define ANGLE_SCALE_F ((float)((3.14159265358979323846/2.0)/90.0))

// ---- device scratch (static; no allocations) ----
__device__ float4   g_dec[BNc*2];        // per anchor: {x,y,a,b},{c,det,lse,0}
__device__ int      g_fgm[BNc];          // (count<<20) | bm  (bm valid iff count==1)
__device__ int      g_m[BNc];
__device__ float    g_al[BNc];
__device__ float    g_iou[BNc];
__device__ unsigned g_mark[BNc];         // epoch-stamped "queued for decode"
__device__ unsigned g_epoch;
__device__ float4   g_gt[Bc*Mc*3];       // per GT: {cx,cy,a,b},{c,det,hw,hh},{ca,sa,ang,0}
__device__ unsigned g_maxal[Bc*Mc], g_maxiou[Bc*Mc];
__device__ int      g_cand[Bc*Mc*CAND];  // per-GT candidate anchor ids (within image)
__device__ int      g_ccnt[Bc*Mc];
__device__ int      g_dlist[BNc];        // deduped decode worklist
__device__ int      g_ndec;
__device__ int      g_npos;
__device__ int      g_done;
__device__ int      g_plist[16384];
__device__ double   g_negpart[NEGBLK];
__device__ double   g_ppart[POSBLK*5];

// ProbIoU Hellinger distance (eps=1e-3), fast transcendentals (err ~1e-6, budget 1e-3)
__device__ __forceinline__ float probiou_hd(float x1, float y1, float a1, float b1, float c1, float d1,
                                            float x2, float y2, float a2, float b2, float c2, float d2){
    float a = a1 + a2, b = b1 + b2, c = c1 + c2;
    float denom = a*b - c*c + 1e-3f;
    float dy = y1 - y2, dx = x1 - x2;
    float rd = __fdividef(1.0f, denom);
    float t1 = (a*dy*dy + b*dx*dx) * rd * 0.25f;
    float t2 = c * (-dx) * dy * rd * 0.5f;
    float t3 = 0.5f * __logf(denom * __fdividef(1.0f, 4.0f*sqrtf(d1*d2) + 1e-3f) + 1e-3f);
    float bd = fminf(fmaxf(t1 + t2 + t3, 1e-3f), 100.0f);
    return sqrtf(1.0f - __expf(-bd) + 1e-7f);
}

__device__ __forceinline__ float fast_sig(float x){
    return __fdividef(1.0f, 1.0f + __expf(-x));
}

// block reduction of a double over 256 threads; result valid on thread 0
__device__ __forceinline__ double block_red(double v){
    __shared__ double sred[8];
    #pragma unroll
    for (int o = 16; o; o >>= 1) v += __shfl_down_sync(0xffffffffu, v, o);
    int w = threadIdx.x >> 5, l = threadIdx.x & 31;
    if (l == 0) sred[w] = v;
    __syncthreads();
    if (w == 0){
        v = (l < 8) ? sred[l] : 0.0;
        #pragma unroll
        for (int o = 4; o; o >>= 1) v += __shfl_down_sync(0xffffffffu, v, o);
    }
    __syncthreads();
    return v;
}

// ---- K0: counters/epoch + pure-negative focal BCE over all (anchor,class) ----
__global__ void k_prep(const float* __restrict__ cls){
    if (blockIdx.x == 0 && threadIdx.x == 0){
        g_epoch += 1u; g_npos = 0; g_done = 0; g_ndec = 0;
    }
    __shared__ float sc[256*Cc];
    size_t base = (size_t)blockIdx.x * (256*Cc);
    const float4* src = (const float4*)(cls + base);
    #pragma unroll
    for (int j = threadIdx.x; j < (256*Cc)/4; j += 256) ((float4*)sc)[j] = src[j];
    __syncthreads();
    float acc = 0.0f;
    int r = threadIdx.x * Cc;
    #pragma unroll
    for (int c = 0; c < Cc; c++){
        float x  = sc[r + c];
        float em = __expf(-fabsf(x));
        float t  = 1.0f + em;
        float sp = fmaxf(x, 0.0f) + __logf(t);          // softplus(x) = bce(x, t=0)
        float sg = ((x >= 0.0f) ? 1.0f : em) * __fdividef(1.0f, t);
        acc += 0.75f * sg * sg * sp;
    }
    double v = block_red((double)acc);
    if (threadIdx.x == 0) g_negpart[blockIdx.x] = v;
}

// ---- K1: warp-per-GT: GT prep + candidate gather + deduped decode worklist ----
__global__ void __launch_bounds__(128) k_gather(const float* __restrict__ gtb,
                                                const float* __restrict__ vm){
    __shared__ int scnt[4];
    int w    = threadIdx.x >> 5;
    int lane = threadIdx.x & 31;
    int bm   = blockIdx.x*4 + w;
    int b    = bm >> 6;
    unsigned ep = g_epoch;

    // all lanes redundantly compute GT-derived values (broadcast loads)
    const float* g = gtb + bm*5;
    float gcx = g[0], gcy = g[1], gw_ = g[2], gh_ = g[3], gang = g[4];
    float ca = __cosf(gang), sa = __sinf(gang);
    float A = gw_*gw_/12.0f, B = gh_*gh_/12.0f;
    float ga = A*ca*ca + B*sa*sa;
    float gb = A*sa*sa + B*ca*ca;
    float gc = (A - B)*ca*sa;
    float gd = fmaxf(ga*gb - gc*gc, 0.0f);
    float hw = gw_*0.5f, hh = gh_*0.5f;
    if (lane == 0){
        g_gt[bm*3+0] = make_float4(gcx, gcy, ga, gb);
        g_gt[bm*3+1] = make_float4(gc, gd, hw, hh);
        g_gt[bm*3+2] = make_float4(ca, sa, gang, 0.0f);
        g_maxal[bm] = 0u; g_maxiou[bm] = 0u;
        scnt[w] = 0;
    }
    __syncwarp();
    if (vm[bm] == 0.0f){
        if (lane == 0) g_ccnt[bm] = 0;
        return;
    }
    float hx = hw*ca + hh*sa;   // AABB half extents (ca,sa >= 0 for ang in [0,pi/2))
    float hy = hw*sa + hh*ca;

    #pragma unroll
    for (int L = 0; L < 3; L++){
        float st  = (L == 0) ? 8.0f : (L == 1) ? 16.0f : 32.0f;
        int npl   = (L == 0) ? 128  : (L == 1) ? 64   : 32;
        int baseN = (L == 0) ? 0    : (L == 1) ? 16384 : 20480;
        float is  = __fdividef(1.0f, st);
        int ix0 = max(0,     (int)((gcx - hx)*is - 0.5f) - 1);
        int ix1 = min(npl-1, (int)((gcx + hx)*is - 0.5f) + 1);
        int iy0 = max(0,     (int)((gcy - hy)*is - 0.5f) - 1);
        int iy1 = min(npl-1, (int)((gcy + hy)*is - 0.5f) + 1);
        int nx = ix1 - ix0 + 1, ny = iy1 - iy0 + 1;
        if (nx <= 0 || ny <= 0) continue;
        int tot = nx*ny;
        for (int j = lane; j < tot; j += 32){
            int ix = ix0 + j % nx, iy = iy0 + j / nx;
            float ax = (ix + 0.5f)*st, ay = (iy + 0.5f)*st;
            float dx = ax - gcx, dy = ay - gcy;
            float xr = dx*ca + dy*sa;
            float yr = dy*ca - dx*sa;
            if (fabsf(xr) < hw && fabsf(yr) < hh){
                int n = baseN + iy*npl + ix;
                int p = atomicAdd(&scnt[w], 1);
                if (p < CAND) g_cand[bm*CAND + p] = n;
                int idx = b*Nc + n;
                if (atomicExch(&g_mark[idx], ep) != ep){   // first marker this run
                    g_fgm[idx] = 0;
                    int d = atomicAdd(&g_ndec, 1);
                    g_dlist[d] = idx;
                }
            }
        }
    }
    __syncwarp();
    if (lane == 0) g_ccnt[bm] = min(scnt[w], CAND);
}

// ---- K2: sparse decode over worklist; per-row serial softmax (contiguous 364B read) ----
__global__ void k_decode(const float* __restrict__ raw, const float* __restrict__ reg){
    int nd = g_ndec;
    for (int i = blockIdx.x*blockDim.x + threadIdx.x; i < nd; i += gridDim.x*blockDim.x){
        int row = g_dlist[i];
        const float* rr = raw + (size_t)row*ABp;
        float s = 0.0f, wk = 0.0f;
        #pragma unroll
        for (int k = 0; k < ABp; k++){
            float e = __expf(__ldg(rr + k));
            s  += e;
            wk  = fmaf((float)k, e, wk);
        }
        float ang = __fdividef(wk, s) * ANGLE_SCALE_F;
        float lse = __logf(s);
        float4 rd = *(const float4*)(reg + (size_t)row*4);
        float offx = (rd.z - rd.x)*0.5f, offy = (rd.w - rd.y)*0.5f;
        float c = __cosf(ang), sn = __sinf(ang);
        int n = row % Nc;
        float ax, ay, st;
        if (n < 16384)      { int ii = n;         ax = ((ii & 127) + 0.5f)*8.0f;  ay = ((ii >> 7) + 0.5f)*8.0f;  st = 8.0f;  }
        else if (n < 20480) { int ii = n - 16384; ax = ((ii &  63) + 0.5f)*16.0f; ay = ((ii >> 6) + 0.5f)*16.0f; st = 16.0f; }
        else                { int ii = n - 20480; ax = ((ii &  31) + 0.5f)*32.0f; ay = ((ii >> 5) + 0.5f)*32.0f; st = 32.0f; }
        float X = (offx*c - offy*sn)*st + ax;
        float Y = (offx*sn + offy*c)*st + ay;
        float W = (rd.x + rd.z)*st, H = (rd.y + rd.w)*st;
        float A = W*W/12.0f, Bv = H*H/12.0f;
        float pa = A*c*c + Bv*sn*sn;
        float pb = A*sn*sn + Bv*c*c;
        float pc = (A - Bv)*c*sn;
        float pd = fmaxf(pa*pb - pc*pc, 0.0f);
        g_dec[2*row]   = make_float4(X, Y, pa, pb);
        g_dec[2*row+1] = make_float4(pc, pd, lse, 0.0f);
    }
}

// ---- K3: warp-per-GT: lane-parallel align + top-13 selection (claims store al/iou) ----
__global__ void __launch_bounds__(128) k_topk(const float* __restrict__ cls,
                                              const int*   __restrict__ gtl,
                                              const float* __restrict__ vm){
    __shared__ float cv[4][CAND];
    __shared__ float siou[4][CAND];
    __shared__ int   sci[4][CAND];
    int w    = threadIdx.x >> 5;
    int lane = threadIdx.x & 31;
    int bm   = blockIdx.x*4 + w;
    if (vm[bm] == 0.0f) return;
    int b = bm >> 6;
    int count = g_ccnt[bm];
    if (count == 0) return;
    int lbl = gtl[bm];

    float4 q0 = g_gt[3*bm], q1 = g_gt[3*bm+1];
    float gcx = q0.x, gcy = q0.y, ga = q0.z, gb = q0.w;
    float gc = q1.x, gd = q1.y;

    // lane-parallel align over candidates (g_dec L2-resident)
    for (int j = lane; j < count; j += 32){
        int n = g_cand[bm*CAND + j];
        sci[w][j] = n;
        int idx = b*Nc + n;
        float4 p0 = g_dec[2*idx], p1 = g_dec[2*idx+1];
        float hd = probiou_hd(gcx, gcy, ga, gb, gc, gd,
                              p0.x, p0.y, p0.z, p0.w, p1.x, p1.y);
        float iou = fmaxf(1.0f - hd, 0.0f);
        float sg = fast_sig(cls[(size_t)idx*Cc + lbl]);
        float i2 = iou*iou;
        cv[w][j]   = sg * i2*i2*i2;                // score^1 * iou^6
        siou[w][j] = iou;
    }
    __syncwarp();

    // 13 rounds max-extraction (value desc, index asc tiebreak == lax.top_k)
    int K = min(count, 13);
    for (int k = 0; k < K; k++){
        float bv = -1.0f; int bi = 0x7fffffff, bp = -1;
        for (int j = lane; j < count; j += 32){
            float v = cv[w][j];
            if (v > bv || (v == bv && sci[w][j] < bi)){ bv = v; bi = sci[w][j]; bp = j; }
        }
        #pragma unroll
        for (int o = 16; o; o >>= 1){
            float ov = __shfl_xor_sync(0xffffffffu, bv, o);
            int   oi = __shfl_xor_sync(0xffffffffu, bi, o);
            int   op = __shfl_xor_sync(0xffffffffu, bp, o);
            if (ov > bv || (ov == bv && oi < bi)){ bv = ov; bi = oi; bp = op; }
        }
        if (bv <= EPSA) break;                     // valid = topv > EPS
        if (lane == 0){
            int idx = b*Nc + bi;
            int old = atomicAdd(&g_fgm[idx], (1 << 20) | bm);
            if ((old >> 20) == 0){                 // first claim -> append once
                int p = atomicAdd(&g_npos, 1);
                g_plist[p] = idx;
            }
            g_al[idx]  = bv;                       // valid iff final count==1
            g_iou[idx] = siou[w][bp];
            cv[w][bp] = -2.0f;
        }
        __syncwarp();
    }
}

// ---- K4: resolve positives; cnt==1 reuses stored al/iou, cnt>1 argmax-IoU over 64 GTs ----
__global__ void k_resolve(const float* __restrict__ cls, const int* __restrict__ gtl){
    int i = blockIdx.x*256 + threadIdx.x;
    if (i >= g_npos) return;
    int idx = g_plist[i];
    int b = idx / Nc;
    int fgm = g_fgm[idx];
    int m; float iou, al;
    if ((fgm >> 20) == 1){
        m   = fgm & 63;
        al  = g_al[idx];
        iou = g_iou[idx];
    } else {
        float4 p0 = g_dec[2*idx], p1 = g_dec[2*idx+1];
        float bv = -1.0f; int bm_ = 0;
        #pragma unroll 4
        for (int mm = 0; mm < 64; mm++){
            float4 q0 = g_gt[3*(b*64+mm)], q1 = g_gt[3*(b*64+mm)+1];
            float hd = probiou_hd(q0.x, q0.y, q0.z, q0.w, q1.x, q1.y,
                                  p0.x, p0.y, p0.z, p0.w, p1.x, p1.y);
            float io = fmaxf(1.0f - hd, 0.0f);
            if (io > bv){ bv = io; bm_ = mm; }     // first-max == jnp.argmax
        }
        m = bm_; iou = bv;
        int label = gtl[b*64 + m];
        float sg = fast_sig(cls[(size_t)idx*Cc + label]);
        float i2 = iou*iou;
        al = sg * i2*i2*i2;
        g_al[idx] = al;
    }
    g_m[idx] = m;
    atomicMax(&g_maxal [b*64 + m], __float_as_uint(al));
    atomicMax(&g_maxiou[b*64 + m], __float_as_uint(iou));
}

// ---- K5: positive losses + (last block) final reduce ----
__global__ void k_pos(const float* __restrict__ cls, const float* __restrict__ raw,
                      const int* __restrict__ gtl, float* __restrict__ out){
    int tid = threadIdx.x;
    int i = blockIdx.x*256 + tid;
    double dC = 0.0, dB = 0.0, dA = 0.0, dS = 0.0, dN = 0.0;
    if (i < g_npos){
        int idx = g_plist[i];
        int b = idx / Nc;
        int m = g_m[idx];
        int gi = b*64 + m;
        int label = gtl[gi];
        float ma = __uint_as_float(g_maxal [gi]);
        float mi = __uint_as_float(g_maxiou[gi]);
        float na = g_al[idx] * mi * __fdividef(1.0f, ma + EPSA);
        // cls correction: replace the negative-assumed label term with the true one
        float x  = cls[(size_t)idx*Cc + label];
        float em = __expf(-fabsf(x));
        float t  = 1.0f + em;
        float sp = fmaxf(x, 0.0f) + __logf(t);
        float sg = ((x >= 0.0f) ? 1.0f : em) * __fdividef(1.0f, t);
        dC = (double)((sp - x*na)*na - sp*0.75f*sg*sg);
        // box loss
        float4 p0 = g_dec[2*idx], p1 = g_dec[2*idx+1];
        float4 q0 = g_gt[3*gi], q1 = g_gt[3*gi+1], q2 = g_gt[3*gi+2];
        float hd = probiou_hd(p0.x, p0.y, p0.z, p0.w, p1.x, p1.y,
                              q0.x, q0.y, q0.z, q0.w, q1.x, q1.y);
        dB = (double)(hd * na);
        // angle CE
        float tA = q2.z / ANGLE_SCALE_F;
        tA = fminf(fmaxf(tA, 0.0f), 89.99f);
        int li = (int)tA;
        int ri = min(li + 1, 90);
        float lw = (float)ri - tA;
        float rw = 1.0f - lw;
        float lse = p1.z;
        const float* ra = raw + (size_t)idx*ABp;
        dA = (double)((lse - ra[li])*lw + (lse - ra[ri])*rw);
        dS = (double)na;
        dN = 1.0;
    }
    double vals[5] = {dC, dB, dA, dS, dN};
    #pragma unroll
    for (int k = 0; k < 5; k++){
        double v = block_red(vals[k]);
        if (tid == 0) g_ppart[blockIdx.x*5 + k] = v;
    }
    __threadfence();
    __shared__ int slast;
    if (tid == 0) slast = (atomicAdd(&g_done, 1) == POSBLK - 1) ? 1 : 0;
    __syncthreads();
    if (!slast) return;
    __threadfence();
    // final deterministic reduce
    double accC = 0.0;
    for (int j = tid; j < NEGBLK; j += 256) accC += g_negpart[j];
    double acc[5] = {0, 0, 0, 0, 0};
    for (int j = tid; j < POSBLK; j += 256){
        #pragma unroll
        for (int k = 0; k < 5; k++) acc[k] += g_ppart[j*5 + k];
    }
    __shared__ double fin[6];
    double v = block_red(accC);
    if (tid == 0) fin[0] = v;
    #pragma unroll
    for (int k = 0; k < 5; k++){
        v = block_red(acc[k]);
        if (tid == 0) fin[1 + k] = v;
    }
    __syncthreads();
    if (tid == 0){
        double ss   = fmax(fin[4], 1.0);            // score_sum
        double lcls = (fin[0] + fin[1]) / ss;       // neg sum + pos corrections
        double lbox = fin[2] / ss;
        double np_  = fmax(fin[5], 1.0);
        double lang = fin[3] / np_;
        out[0] = (float)(lcls + 2.5*lbox + 0.05*lang);
        out[1] = (float)lcls;
        out[2] = (float)lbox;
        out[3] = (float)lang;
    }
}

extern "C" void kernel_launch(void* const* d_in, const int* in_sizes, int n_in,
                              void* d_out, int out_size){
    const float* cls = (const float*)d_in[0];
    const float* reg = (const float*)d_in[1];
    const float* raw = (const float*)d_in[2];
    const int*   gtl = (const int*)  d_in[3];
    const float* gtb = (const float*)d_in[4];
    const float* vm  = (const float*)d_in[5];

    k_prep   <<<NEGBLK, 256>>>(cls);
    k_gather <<<Bc*Mc/4, 128>>>(gtb, vm);
    k_decode <<<296, 256>>>(raw, reg);
    k_topk   <<<Bc*Mc/4, 128>>>(cls, gtl, vm);
    k_resolve<<<POSBLK, 256>>>(cls, gtl);
    k_pos    <<<POSBLK, 256>>>(cls, raw, gtl, (float*)d_out);
}

// round 6
// speedup vs baseline: 1.2031x; 1.2031x over previous
#include <cuda_runtime.h>
#include <math.h>
#include <float.h>
#include <stdint.h>

// Problem constants (fixed by setup_inputs)
#define Bc 16
#define Nc 21504           // 128^2 + 64^2 + 32^2 anchors
#define Mc 64
#define Cc 15
#define ABp 91             // angle bins + 1
#define BNc (Bc*Nc)        // 344064
#define NEGBLK (BNc/256)   // 1344
#define POSBLK 52          // 52*256 = 13312 >= max positives
#define CAND 768           // per-GT candidate cap (max in-box cells ~525)
#define EPSA 1e-9f
#define ANGLE_SCALE_F ((float)((3.14159265358979323846/2.0)/90.0))

// ---- device scratch (static; no allocations) ----
__device__ float4   g_dec[BNc*2];        // per anchor: {x,y,a,b},{c,det,lse,0}
__device__ int      g_fgm[BNc];          // (count<<20) | bm  (bm valid iff count==1)
__device__ int      g_m[BNc];
__device__ float    g_al[BNc];
__device__ float    g_iou[BNc];
__device__ unsigned g_mark[BNc];         // epoch-stamped "queued for decode"
__device__ unsigned g_epoch;
__device__ float4   g_gt[Bc*Mc*3];       // per GT: {cx,cy,a,b},{c,det,hw,hh},{ca,sa,ang,0}
__device__ unsigned g_maxal[Bc*Mc], g_maxiou[Bc*Mc];
__device__ int      g_cand[Bc*Mc*CAND];  // per-GT candidate anchor ids (within image)
__device__ int      g_ccnt[Bc*Mc];
__device__ int      g_dlist[BNc];        // deduped decode worklist
__device__ int      g_ndec;
__device__ int      g_npos;
__device__ int      g_done;
__device__ int      g_plist[16384];
__device__ double   g_negpart[NEGBLK];
__device__ double   g_ppart[POSBLK*5];

// ProbIoU Hellinger distance (eps=1e-3), fast transcendentals (err ~1e-6, budget 1e-3)
__device__ __forceinline__ float probiou_hd(float x1, float y1, float a1, float b1, float c1, float d1,
                                            float x2, float y2, float a2, float b2, float c2, float d2){
    float a = a1 + a2, b = b1 + b2, c = c1 + c2;
    float denom = a*b - c*c + 1e-3f;
    float dy = y1 - y2, dx = x1 - x2;
    float rd = __fdividef(1.0f, denom);
    float t1 = (a*dy*dy + b*dx*dx) * rd * 0.25f;
    float t2 = c * (-dx) * dy * rd * 0.5f;
    float t3 = 0.5f * __logf(denom * __fdividef(1.0f, 4.0f*sqrtf(d1*d2) + 1e-3f) + 1e-3f);
    float bd = fminf(fmaxf(t1 + t2 + t3, 1e-3f), 100.0f);
    return sqrtf(1.0f - __expf(-bd) + 1e-7f);
}

__device__ __forceinline__ float fast_sig(float x){
    return __fdividef(1.0f, 1.0f + __expf(-x));
}

// block reduction of a double over 256 threads; result valid on thread 0
__device__ __forceinline__ double block_red(double v){
    __shared__ double sred[8];
    #pragma unroll
    for (int o = 16; o; o >>= 1) v += __shfl_down_sync(0xffffffffu, v, o);
    int w = threadIdx.x >> 5, l = threadIdx.x & 31;
    if (l == 0) sred[w] = v;
    __syncthreads();
    if (w == 0){
        v = (l < 8) ? sred[l] : 0.0;
        #pragma unroll
        for (int o = 4; o; o >>= 1) v += __shfl_down_sync(0xffffffffu, v, o);
    }
    __syncthreads();
    return v;
}

// ---- K0: counters/epoch + pure-negative focal BCE over all (anchor,class) ----
__global__ void k_prep(const float* __restrict__ cls){
    if (blockIdx.x == 0 && threadIdx.x == 0){
        g_epoch += 1u; g_npos = 0; g_done = 0; g_ndec = 0;
    }
    __shared__ float sc[256*Cc];
    size_t base = (size_t)blockIdx.x * (256*Cc);
    const float4* src = (const float4*)(cls + base);
    #pragma unroll
    for (int j = threadIdx.x; j < (256*Cc)/4; j += 256) ((float4*)sc)[j] = src[j];
    __syncthreads();
    float acc = 0.0f;
    int r = threadIdx.x * Cc;
    #pragma unroll
    for (int c = 0; c < Cc; c++){
        float x  = sc[r + c];
        float em = __expf(-fabsf(x));
        float t  = 1.0f + em;
        float sp = fmaxf(x, 0.0f) + __logf(t);          // softplus(x) = bce(x, t=0)
        float sg = ((x >= 0.0f) ? 1.0f : em) * __fdividef(1.0f, t);
        acc += 0.75f * sg * sg * sp;
    }
    double v = block_red((double)acc);
    if (threadIdx.x == 0) g_negpart[blockIdx.x] = v;
}

// ---- K1: warp-per-GT: GT prep + candidate gather + deduped decode worklist ----
__global__ void __launch_bounds__(128) k_gather(const float* __restrict__ gtb,
                                                const float* __restrict__ vm){
    __shared__ int scnt[4];
    int w    = threadIdx.x >> 5;
    int lane = threadIdx.x & 31;
    int bm   = blockIdx.x*4 + w;
    int b    = bm >> 6;
    unsigned ep = g_epoch;

    const float* g = gtb + bm*5;
    float gcx = g[0], gcy = g[1], gw_ = g[2], gh_ = g[3], gang = g[4];
    float ca = __cosf(gang), sa = __sinf(gang);
    float A = gw_*gw_/12.0f, B = gh_*gh_/12.0f;
    float ga = A*ca*ca + B*sa*sa;
    float gb = A*sa*sa + B*ca*ca;
    float gc = (A - B)*ca*sa;
    float gd = fmaxf(ga*gb - gc*gc, 0.0f);
    float hw = gw_*0.5f, hh = gh_*0.5f;
    if (lane == 0){
        g_gt[bm*3+0] = make_float4(gcx, gcy, ga, gb);
        g_gt[bm*3+1] = make_float4(gc, gd, hw, hh);
        g_gt[bm*3+2] = make_float4(ca, sa, gang, 0.0f);
        g_maxal[bm] = 0u; g_maxiou[bm] = 0u;
        scnt[w] = 0;
    }
    __syncwarp();
    if (vm[bm] == 0.0f){
        if (lane == 0) g_ccnt[bm] = 0;
        return;
    }
    float hx = hw*ca + hh*sa;   // AABB half extents (ca,sa >= 0 for ang in [0,pi/2))
    float hy = hw*sa + hh*ca;

    #pragma unroll
    for (int L = 0; L < 3; L++){
        float st  = (L == 0) ? 8.0f : (L == 1) ? 16.0f : 32.0f;
        int npl   = (L == 0) ? 128  : (L == 1) ? 64   : 32;
        int baseN = (L == 0) ? 0    : (L == 1) ? 16384 : 20480;
        float is  = __fdividef(1.0f, st);
        int ix0 = max(0,     (int)((gcx - hx)*is - 0.5f) - 1);
        int ix1 = min(npl-1, (int)((gcx + hx)*is - 0.5f) + 1);
        int iy0 = max(0,     (int)((gcy - hy)*is - 0.5f) - 1);
        int iy1 = min(npl-1, (int)((gcy + hy)*is - 0.5f) + 1);
        int nx = ix1 - ix0 + 1, ny = iy1 - iy0 + 1;
        if (nx <= 0 || ny <= 0) continue;
        int tot = nx*ny;
        for (int j = lane; j < tot; j += 32){
            int ix = ix0 + j % nx, iy = iy0 + j / nx;
            float ax = (ix + 0.5f)*st, ay = (iy + 0.5f)*st;
            float dx = ax - gcx, dy = ay - gcy;
            float xr = dx*ca + dy*sa;
            float yr = dy*ca - dx*sa;
            if (fabsf(xr) < hw && fabsf(yr) < hh){
                int n = baseN + iy*npl + ix;
                int p = atomicAdd(&scnt[w], 1);
                if (p < CAND) g_cand[bm*CAND + p] = n;
                int idx = b*Nc + n;
                if (atomicExch(&g_mark[idx], ep) != ep){   // first marker this run
                    g_fgm[idx] = 0;
                    int d = atomicAdd(&g_ndec, 1);
                    g_dlist[d] = idx;
                }
            }
        }
    }
    __syncwarp();
    if (lane == 0) g_ccnt[bm] = min(scnt[w], CAND);
}

// ---- K2: sparse decode, 8 lanes per row (coalesced 32B group reads, MLP 12) ----
__global__ void __launch_bounds__(256) k_decode(const float* __restrict__ raw,
                                                const float* __restrict__ reg){
    int nd = g_ndec;
    int t  = threadIdx.x & 7;
    int g0 = (blockIdx.x*blockDim.x + threadIdx.x) >> 3;
    int ng = (gridDim.x*blockDim.x) >> 3;
    for (int i = g0; i < nd; i += ng){
        int row = g_dlist[i];
        const float* rr = raw + (size_t)row*ABp;
        float s = 0.0f, wk = 0.0f;
        #pragma unroll
        for (int k2 = 0; k2 < 12; k2++){
            int kk = t + (k2 << 3);
            if (kk < ABp){
                float e = __expf(rr[kk]);
                s += e;
                wk = fmaf((float)kk, e, wk);
            }
        }
        #pragma unroll
        for (int o = 1; o < 8; o <<= 1){
            s  += __shfl_xor_sync(0xffffffffu, s,  o);
            wk += __shfl_xor_sync(0xffffffffu, wk, o);
        }
        if (t == 0){
            float ang = __fdividef(wk, s) * ANGLE_SCALE_F;
            float lse = __logf(s);
            float4 rd = *(const float4*)(reg + (size_t)row*4);
            float offx = (rd.z - rd.x)*0.5f, offy = (rd.w - rd.y)*0.5f;
            float c = __cosf(ang), sn = __sinf(ang);
            int n = row % Nc;
            float ax, ay, st;
            if (n < 16384)      { int ii = n;         ax = ((ii & 127) + 0.5f)*8.0f;  ay = ((ii >> 7) + 0.5f)*8.0f;  st = 8.0f;  }
            else if (n < 20480) { int ii = n - 16384; ax = ((ii &  63) + 0.5f)*16.0f; ay = ((ii >> 6) + 0.5f)*16.0f; st = 16.0f; }
            else                { int ii = n - 20480; ax = ((ii &  31) + 0.5f)*32.0f; ay = ((ii >> 5) + 0.5f)*32.0f; st = 32.0f; }
            float X = (offx*c - offy*sn)*st + ax;
            float Y = (offx*sn + offy*c)*st + ay;
            float W = (rd.x + rd.z)*st, H = (rd.y + rd.w)*st;
            float A = W*W/12.0f, Bv = H*H/12.0f;
            float pa = A*c*c + Bv*sn*sn;
            float pb = A*sn*sn + Bv*c*c;
            float pc = (A - Bv)*c*sn;
            float pd = fmaxf(pa*pb - pc*pc, 0.0f);
            g_dec[2*row]   = make_float4(X, Y, pa, pb);
            g_dec[2*row+1] = make_float4(pc, pd, lse, 0.0f);
        }
    }
}

// ---- K3: block-per-GT: parallel align into smem, then register top-13 + parallel claims ----
__global__ void __launch_bounds__(256) k_assign(const float* __restrict__ cls,
                                                const int*   __restrict__ gtl){
    __shared__ float sv[CAND];
    __shared__ int   sn[CAND];
    __shared__ float sio[CAND];
    int bm = blockIdx.x;
    int b  = bm >> 6;
    int count = g_ccnt[bm];
    if (count == 0) return;
    int lbl = gtl[bm];
    float4 q0 = g_gt[3*bm], q1 = g_gt[3*bm+1];
    float gcx = q0.x, gcy = q0.y, ga = q0.z, gb = q0.w;
    float gc = q1.x, gd = q1.y;

    // all 8 warps: lane-parallel align over candidates (g_dec L2-resident)
    for (int j = threadIdx.x; j < count; j += 256){
        int n = g_cand[bm*CAND + j];
        int idx = b*Nc + n;
        float4 p0 = g_dec[2*idx], p1 = g_dec[2*idx+1];
        float hd = probiou_hd(gcx, gcy, ga, gb, gc, gd,
                              p0.x, p0.y, p0.z, p0.w, p1.x, p1.y);
        float iou = fmaxf(1.0f - hd, 0.0f);
        float sg = fast_sig(cls[(size_t)idx*Cc + lbl]);
        float i2 = iou*iou;
        sv[j]  = sg * i2*i2*i2;                // score^1 * iou^6
        sn[j]  = n;
        sio[j] = iou;
    }
    __syncthreads();
    if (threadIdx.x >= 32) return;
    int lane = threadIdx.x;

    // per-lane register top-13 (desc value, asc index tiebreak == lax.top_k order)
    float lv[13]; int ln_[13]; float lio[13];
    #pragma unroll
    for (int k = 0; k < 13; k++){ lv[k] = -1.0f; ln_[k] = 0x7fffffff; lio[k] = 0.0f; }
    for (int j = lane; j < count; j += 32){
        float v = sv[j];
        if (v <= EPSA) continue;               // valid = topv > EPS
        int n = sn[j]; float io = sio[j];
        if (v > lv[12] || (v == lv[12] && n < ln_[12])){
            lv[12] = v; ln_[12] = n; lio[12] = io;
            #pragma unroll
            for (int k = 12; k > 0; k--){
                bool sw = (lv[k] > lv[k-1]) || (lv[k] == lv[k-1] && ln_[k] < ln_[k-1]);
                if (sw){
                    float tv = lv[k-1];  lv[k-1]  = lv[k];  lv[k]  = tv;
                    int   tn = ln_[k-1]; ln_[k-1] = ln_[k]; ln_[k] = tn;
                    float ti = lio[k-1]; lio[k-1] = lio[k]; lio[k] = ti;
                }
            }
        }
    }

    // 13 merge rounds: butterfly argmax over list heads; winner distributed to lane k
    float myV = -1.0f; int myN = 0; float myIo = 0.0f;
    int nsel = 0;
    for (int k = 0; k < 13; k++){
        float bv = lv[0]; int bn = ln_[0]; float bio = lio[0];
        #pragma unroll
        for (int o = 16; o; o >>= 1){
            float ov = __shfl_xor_sync(0xffffffffu, bv, o);
            int   on = __shfl_xor_sync(0xffffffffu, bn, o);
            float oo = __shfl_xor_sync(0xffffffffu, bio, o);
            if (ov > bv || (ov == bv && on < bn)){ bv = ov; bn = on; bio = oo; }
        }
        if (bv <= EPSA) break;
        if (lane == k){ myV = bv; myN = bn; myIo = bio; }
        nsel = k + 1;
        if (ln_[0] == bn && lv[0] == bv){      // winner lane pops its head
            #pragma unroll
            for (int k2 = 0; k2 < 12; k2++){ lv[k2] = lv[k2+1]; ln_[k2] = ln_[k2+1]; lio[k2] = lio[k2+1]; }
            lv[12] = -1.0f; ln_[12] = 0x7fffffff; lio[12] = 0.0f;
        }
    }

    // parallel claims: lanes 0..nsel-1 each claim one selected anchor
    if (lane < nsel){
        int idx = b*Nc + myN;
        int old = atomicAdd(&g_fgm[idx], (1 << 20) | bm);
        if ((old >> 20) == 0){                 // first claim -> append once
            int p = atomicAdd(&g_npos, 1);
            g_plist[p] = idx;
        }
        g_al[idx]  = myV;                      // valid iff final count==1
        g_iou[idx] = myIo;
    }
}

// ---- K4: resolve positives; cnt==1 reuses stored al/iou, cnt>1 argmax-IoU over 64 GTs ----
__global__ void k_resolve(const float* __restrict__ cls, const int* __restrict__ gtl){
    int i = blockIdx.x*256 + threadIdx.x;
    if (i >= g_npos) return;
    int idx = g_plist[i];
    int b = idx / Nc;
    int fgm = g_fgm[idx];
    int m; float iou, al;
    if ((fgm >> 20) == 1){
        m   = fgm & 63;
        al  = g_al[idx];
        iou = g_iou[idx];
    } else {
        float4 p0 = g_dec[2*idx], p1 = g_dec[2*idx+1];
        float bv = -1.0f; int bm_ = 0;
        #pragma unroll 4
        for (int mm = 0; mm < 64; mm++){
            float4 q0 = g_gt[3*(b*64+mm)], q1 = g_gt[3*(b*64+mm)+1];
            float hd = probiou_hd(q0.x, q0.y, q0.z, q0.w, q1.x, q1.y,
                                  p0.x, p0.y, p0.z, p0.w, p1.x, p1.y);
            float io = fmaxf(1.0f - hd, 0.0f);
            if (io > bv){ bv = io; bm_ = mm; }     // first-max == jnp.argmax
        }
        m = bm_; iou = bv;
        int label = gtl[b*64 + m];
        float sg = fast_sig(cls[(size_t)idx*Cc + label]);
        float i2 = iou*iou;
        al = sg * i2*i2*i2;
        g_al[idx] = al;
    }
    g_m[idx] = m;
    atomicMax(&g_maxal [b*64 + m], __float_as_uint(al));
    atomicMax(&g_maxiou[b*64 + m], __float_as_uint(iou));
}

// ---- K5: positive losses + (last block) final reduce ----
__global__ void k_pos(const float* __restrict__ cls, const float* __restrict__ raw,
                      const int* __restrict__ gtl, float* __restrict__ out){
    int tid = threadIdx.x;
    int i = blockIdx.x*256 + tid;
    double dC = 0.0, dB = 0.0, dA = 0.0, dS = 0.0, dN = 0.0;
    if (i < g_npos){
        int idx = g_plist[i];
        int b = idx / Nc;
        int m = g_m[idx];
        int gi = b*64 + m;
        int label = gtl[gi];
        float ma = __uint_as_float(g_maxal [gi]);
        float mi = __uint_as_float(g_maxiou[gi]);
        float na = g_al[idx] * mi * __fdividef(1.0f, ma + EPSA);
        // cls correction: replace the negative-assumed label term with the true one
        float x  = cls[(size_t)idx*Cc + label];
        float em = __expf(-fabsf(x));
        float t  = 1.0f + em;
        float sp = fmaxf(x, 0.0f) + __logf(t);
        float sg = ((x >= 0.0f) ? 1.0f : em) * __fdividef(1.0f, t);
        dC = (double)((sp - x*na)*na - sp*0.75f*sg*sg);
        // box loss
        float4 p0 = g_dec[2*idx], p1 = g_dec[2*idx+1];
        float4 q0 = g_gt[3*gi], q1 = g_gt[3*gi+1], q2 = g_gt[3*gi+2];
        float hd = probiou_hd(p0.x, p0.y, p0.z, p0.w, p1.x, p1.y,
                              q0.x, q0.y, q0.z, q0.w, q1.x, q1.y);
        dB = (double)(hd * na);
        // angle CE
        float tA = q2.z / ANGLE_SCALE_F;
        tA = fminf(fmaxf(tA, 0.0f), 89.99f);
        int li = (int)tA;
        int ri = min(li + 1, 90);
        float lw = (float)ri - tA;
        float rw = 1.0f - lw;
        float lse = p1.z;
        const float* ra = raw + (size_t)idx*ABp;
        dA = (double)((lse - ra[li])*lw + (lse - ra[ri])*rw);
        dS = (double)na;
        dN = 1.0;
    }
    double vals[5] = {dC, dB, dA, dS, dN};
    #pragma unroll
    for (int k = 0; k < 5; k++){
        double v = block_red(vals[k]);
        if (tid == 0) g_ppart[blockIdx.x*5 + k] = v;
    }
    __threadfence();
    __shared__ int slast;
    if (tid == 0) slast = (atomicAdd(&g_done, 1) == POSBLK - 1) ? 1 : 0;
    __syncthreads();
    if (!slast) return;
    __threadfence();
    // final deterministic reduce
    double accC = 0.0;
    for (int j = tid; j < NEGBLK; j += 256) accC += g_negpart[j];
    double acc[5] = {0, 0, 0, 0, 0};
    for (int j = tid; j < POSBLK; j += 256){
        #pragma unroll
        for (int k = 0; k < 5; k++) acc[k] += g_ppart[j*5 + k];
    }
    __shared__ double fin[6];
    double v = block_red(accC);
    if (tid == 0) fin[0] = v;
    #pragma unroll
    for (int k = 0; k < 5; k++){
        v = block_red(acc[k]);
        if (tid == 0) fin[1 + k] = v;
    }
    __syncthreads();
    if (tid == 0){
        double ss   = fmax(fin[4], 1.0);            // score_sum
        double lcls = (fin[0] + fin[1]) / ss;       // neg sum + pos corrections
        double lbox = fin[2] / ss;
        double np_  = fmax(fin[5], 1.0);
        double lang = fin[3] / np_;
        out[0] = (float)(lcls + 2.5*lbox + 0.05*lang);
        out[1] = (float)lcls;
        out[2] = (float)lbox;
        out[3] = (float)lang;
    }
}

extern "C" void kernel_launch(void* const* d_in, const int* in_sizes, int n_in,
                              void* d_out, int out_size){
    const float* cls = (const float*)d_in[0];
    const float* reg = (const float*)d_in[1];
    const float* raw = (const float*)d_in[2];
    const int*   gtl = (const int*)  d_in[3];
    const float* gtb = (const float*)d_in[4];
    const float* vm  = (const float*)d_in[5];

    k_prep   <<<NEGBLK, 256>>>(cls);
    k_gather <<<Bc*Mc/4, 128>>>(gtb, vm);
    k_decode <<<1024, 256>>>(raw, reg);
    k_assign <<<Bc*Mc, 256>>>(cls, gtl);
    k_resolve<<<POSBLK, 256>>>(cls, gtl);
    k_pos    <<<POSBLK, 256>>>(cls, raw, gtl, (float*)d_out);
}

// round 7
// speedup vs baseline: 1.3212x; 1.0981x over previous
#include <cuda_runtime.h>
#include <math.h>
#include <float.h>
#include <stdint.h>

// Problem constants (fixed by setup_inputs)
#define Bc 16
#define Nc 21504           // 128^2 + 64^2 + 32^2 anchors
#define Mc 64
#define Cc 15
#define ABp 91             // angle bins + 1
#define BNc (Bc*Nc)        // 344064
#define NEGBLK (BNc/256)   // 1344
#define POSBLK 52          // 52*256 = 13312 = max claims (1024 GT * 13)
#define CAND 768           // per-GT candidate cap (max in-box cells ~525)
#define EPSA 1e-9f
#define ANGLE_SCALE_F ((float)((3.14159265358979323846/2.0)/90.0))

// ---- device scratch (static; no allocations) ----
__device__ float4   g_dec[BNc*2];        // per anchor: {x,y,a,b},{c,det,lse,0} (candidates only)
__device__ int      g_fgm[BNc];          // (count<<20) | bm  (bm valid iff count==1)
__device__ int      g_m[BNc];
__device__ float    g_al[BNc];
__device__ float    g_iou[BNc];
__device__ float4   g_gt[Bc*Mc*3];       // per GT: {cx,cy,a,b},{c,det,hw,hh},{ca,sa,ang,0}
__device__ unsigned g_maxal[Bc*Mc], g_maxiou[Bc*Mc];
__device__ int      g_npos;
__device__ int      g_done;
__device__ int      g_sync;
__device__ int      g_plist[16384];
__device__ double   g_negpart[NEGBLK];
__device__ double   g_ppart[POSBLK*5];

// ProbIoU Hellinger distance (eps=1e-3), fast transcendentals (err ~1e-6, budget 1e-3)
__device__ __forceinline__ float probiou_hd(float x1, float y1, float a1, float b1, float c1, float d1,
                                            float x2, float y2, float a2, float b2, float c2, float d2){
    float a = a1 + a2, b = b1 + b2, c = c1 + c2;
    float denom = a*b - c*c + 1e-3f;
    float dy = y1 - y2, dx = x1 - x2;
    float rd = __fdividef(1.0f, denom);
    float t1 = (a*dy*dy + b*dx*dx) * rd * 0.25f;
    float t2 = c * (-dx) * dy * rd * 0.5f;
    float t3 = 0.5f * __logf(denom * __fdividef(1.0f, 4.0f*sqrtf(d1*d2) + 1e-3f) + 1e-3f);
    float bd = fminf(fmaxf(t1 + t2 + t3, 1e-3f), 100.0f);
    return sqrtf(1.0f - __expf(-bd) + 1e-7f);
}

__device__ __forceinline__ float fast_sig(float x){
    return __fdividef(1.0f, 1.0f + __expf(-x));
}

// block reduction of a double over 256 threads; result valid on thread 0
__device__ __forceinline__ double block_red(double v){
    __shared__ double sred[8];
    #pragma unroll
    for (int o = 16; o; o >>= 1) v += __shfl_down_sync(0xffffffffu, v, o);
    int w = threadIdx.x >> 5, l = threadIdx.x & 31;
    if (l == 0) sred[w] = v;
    __syncthreads();
    if (w == 0){
        v = (l < 8) ? sred[l] : 0.0;
        #pragma unroll
        for (int o = 4; o; o >>= 1) v += __shfl_down_sync(0xffffffffu, v, o);
    }
    __syncthreads();
    return v;
}

// ---- K0: counters + g_fgm memset + GT prep + pure-negative focal BCE ----
__global__ void k_prep(const float* __restrict__ cls, const float* __restrict__ gtb){
    int i = blockIdx.x*256 + threadIdx.x;
    g_fgm[i] = 0;
    if (i == 0){ g_npos = 0; g_done = 0; g_sync = 0; }
    if (i < Bc*Mc){
        const float* g = gtb + i*5;
        float cx = g[0], cy = g[1], w = g[2], h = g[3], an = g[4];
        float ca = __cosf(an), sa = __sinf(an);
        float A = w*w/12.0f, B = h*h/12.0f;
        float ga = A*ca*ca + B*sa*sa;
        float gb = A*sa*sa + B*ca*ca;
        float gc = (A - B)*ca*sa;
        float gd = fmaxf(ga*gb - gc*gc, 0.0f);
        g_gt[i*3+0] = make_float4(cx, cy, ga, gb);
        g_gt[i*3+1] = make_float4(gc, gd, w*0.5f, h*0.5f);
        g_gt[i*3+2] = make_float4(ca, sa, an, 0.0f);
        g_maxal[i] = 0u; g_maxiou[i] = 0u;
    }
    // negative-assumed focal BCE over this block's 256 anchors x 15 classes
    __shared__ float sc[256*Cc];
    size_t base = (size_t)blockIdx.x * (256*Cc);
    const float4* src = (const float4*)(cls + base);
    #pragma unroll
    for (int j = threadIdx.x; j < (256*Cc)/4; j += 256) ((float4*)sc)[j] = src[j];
    __syncthreads();
    float acc = 0.0f;
    int r = threadIdx.x * Cc;
    #pragma unroll
    for (int c = 0; c < Cc; c++){
        float x  = sc[r + c];
        float em = __expf(-fabsf(x));
        float t  = 1.0f + em;
        float sp = fmaxf(x, 0.0f) + __logf(t);          // softplus(x) = bce(x, t=0)
        float sg = ((x >= 0.0f) ? 1.0f : em) * __fdividef(1.0f, t);
        acc += 0.75f * sg * sg * sp;
    }
    double v = block_red((double)acc);
    if (threadIdx.x == 0) g_negpart[blockIdx.x] = v;
}

// ---- K1: fused block-per-GT: gather + in-place decode + align + top-13 + claims ----
__global__ void __launch_bounds__(256) k_assign(const float* __restrict__ cls,
                                                const float* __restrict__ raw,
                                                const float* __restrict__ reg,
                                                const int*   __restrict__ gtl,
                                                const float* __restrict__ vm){
    __shared__ int   scand[CAND];
    __shared__ float sv[CAND];
    __shared__ float sio[CAND];
    __shared__ int   scnt;
    int bm = blockIdx.x;
    if (vm[bm] == 0.0f) return;                      // invalid GT: no candidates
    int b   = bm >> 6;
    int tid = threadIdx.x;
    if (tid == 0) scnt = 0;

    float4 q0 = g_gt[3*bm], q1 = g_gt[3*bm+1], q2 = g_gt[3*bm+2];
    float gcx = q0.x, gcy = q0.y, ga = q0.z, gb = q0.w;
    float gc = q1.x, gd = q1.y, hw = q1.z, hh = q1.w;
    float ca = q2.x, sa = q2.y;
    int lbl = gtl[bm];
    float hx = hw*ca + hh*sa;   // AABB half extents (ca,sa >= 0 for ang in [0,pi/2))
    float hy = hw*sa + hh*ca;
    __syncthreads();

    // phase A: gather in-box cells over AABB range of each level
    #pragma unroll
    for (int L = 0; L < 3; L++){
        float st  = (L == 0) ? 8.0f : (L == 1) ? 16.0f : 32.0f;
        int npl   = (L == 0) ? 128  : (L == 1) ? 64   : 32;
        int baseN = (L == 0) ? 0    : (L == 1) ? 16384 : 20480;
        float is  = __fdividef(1.0f, st);
        int ix0 = max(0,     (int)((gcx - hx)*is - 0.5f) - 1);
        int ix1 = min(npl-1, (int)((gcx + hx)*is - 0.5f) + 1);
        int iy0 = max(0,     (int)((gcy - hy)*is - 0.5f) - 1);
        int iy1 = min(npl-1, (int)((gcy + hy)*is - 0.5f) + 1);
        int nx = ix1 - ix0 + 1, ny = iy1 - iy0 + 1;
        if (nx <= 0 || ny <= 0) continue;
        int tot = nx*ny;
        for (int j = tid; j < tot; j += 256){
            int ix = ix0 + j % nx, iy = iy0 + j / nx;
            float ax = (ix + 0.5f)*st, ay = (iy + 0.5f)*st;
            float dx = ax - gcx, dy = ay - gcy;
            float xr = dx*ca + dy*sa;
            float yr = dy*ca - dx*sa;
            if (fabsf(xr) < hw && fabsf(yr) < hh){
                int p = atomicAdd(&scnt, 1);
                if (p < CAND) scand[p] = baseN + iy*npl + ix;
            }
        }
    }
    __syncthreads();
    int count = min(scnt, CAND);
    if (count == 0) return;

    // phase B: decode + align, 8 lanes per candidate row (uniform trip count, full-warp shuffles)
    int t8  = tid & 7;
    int grp = tid >> 3;                              // 0..31
    int iters = (count + 31) >> 5;
    for (int it = 0; it < iters; it++){
        int slot = it*32 + grp;
        bool act = slot < count;
        int n   = act ? scand[slot] : 0;
        int idx = b*Nc + n;
        float s = 0.0f, wk = 0.0f;
        if (act){
            const float* rr = raw + (size_t)idx*ABp;
            #pragma unroll
            for (int k2 = 0; k2 < 12; k2++){
                int kk = t8 + (k2 << 3);
                if (kk < ABp){
                    float e = __expf(rr[kk]);
                    s += e;
                    wk = fmaf((float)kk, e, wk);
                }
            }
        }
        #pragma unroll
        for (int o = 1; o < 8; o <<= 1){
            s  += __shfl_xor_sync(0xffffffffu, s,  o);
            wk += __shfl_xor_sync(0xffffffffu, wk, o);
        }
        if (act && t8 == 0){
            float ang = __fdividef(wk, s) * ANGLE_SCALE_F;
            float lse = __logf(s);
            float4 rd = *(const float4*)(reg + (size_t)idx*4);
            float offx = (rd.z - rd.x)*0.5f, offy = (rd.w - rd.y)*0.5f;
            float c = __cosf(ang), sn = __sinf(ang);
            float ax, ay, st;
            if (n < 16384)      { int ii = n;         ax = ((ii & 127) + 0.5f)*8.0f;  ay = ((ii >> 7) + 0.5f)*8.0f;  st = 8.0f;  }
            else if (n < 20480) { int ii = n - 16384; ax = ((ii &  63) + 0.5f)*16.0f; ay = ((ii >> 6) + 0.5f)*16.0f; st = 16.0f; }
            else                { int ii = n - 20480; ax = ((ii &  31) + 0.5f)*32.0f; ay = ((ii >> 5) + 0.5f)*32.0f; st = 32.0f; }
            float X = (offx*c - offy*sn)*st + ax;
            float Y = (offx*sn + offy*c)*st + ay;
            float W = (rd.x + rd.z)*st, H = (rd.y + rd.w)*st;
            float A = W*W/12.0f, Bv = H*H/12.0f;
            float pa = A*c*c + Bv*sn*sn;
            float pb = A*sn*sn + Bv*c*c;
            float pc = (A - Bv)*c*sn;
            float pd = fmaxf(pa*pb - pc*pc, 0.0f);
            g_dec[2*idx]   = make_float4(X, Y, pa, pb);   // duplicate writes across GTs: identical values
            g_dec[2*idx+1] = make_float4(pc, pd, lse, 0.0f);
            float hd = probiou_hd(gcx, gcy, ga, gb, gc, gd, X, Y, pa, pb, pc, pd);
            float iou = fmaxf(1.0f - hd, 0.0f);
            float sg = fast_sig(cls[(size_t)idx*Cc + lbl]);
            float i2 = iou*iou;
            sv[slot]  = sg * i2*i2*i2;               // score^1 * iou^6
            sio[slot] = iou;
        }
    }
    __syncthreads();
    if (tid >= 32) return;
    int lane = tid;

    // phase C: per-lane register top-13 (desc value, asc index tiebreak == lax.top_k)
    float lv[13]; int ln_[13]; float lio[13];
    #pragma unroll
    for (int k = 0; k < 13; k++){ lv[k] = -1.0f; ln_[k] = 0x7fffffff; lio[k] = 0.0f; }
    for (int j = lane; j < count; j += 32){
        float v = sv[j];
        if (v <= EPSA) continue;                     // valid = topv > EPS
        int n = scand[j]; float io = sio[j];
        if (v > lv[12] || (v == lv[12] && n < ln_[12])){
            lv[12] = v; ln_[12] = n; lio[12] = io;
            #pragma unroll
            for (int k = 12; k > 0; k--){
                bool sw = (lv[k] > lv[k-1]) || (lv[k] == lv[k-1] && ln_[k] < ln_[k-1]);
                if (sw){
                    float tv = lv[k-1];  lv[k-1]  = lv[k];  lv[k]  = tv;
                    int   tn = ln_[k-1]; ln_[k-1] = ln_[k]; ln_[k] = tn;
                    float ti = lio[k-1]; lio[k-1] = lio[k]; lio[k] = ti;
                }
            }
        }
    }

    // 13 butterfly merge rounds; winner k distributed to lane k
    float myV = -1.0f; int myN = 0; float myIo = 0.0f;
    int nsel = 0;
    for (int k = 0; k < 13; k++){
        float bv = lv[0]; int bn = ln_[0]; float bio = lio[0];
        #pragma unroll
        for (int o = 16; o; o >>= 1){
            float ov = __shfl_xor_sync(0xffffffffu, bv, o);
            int   on = __shfl_xor_sync(0xffffffffu, bn, o);
            float oo = __shfl_xor_sync(0xffffffffu, bio, o);
            if (ov > bv || (ov == bv && on < bn)){ bv = ov; bn = on; bio = oo; }
        }
        if (bv <= EPSA) break;
        if (lane == k){ myV = bv; myN = bn; myIo = bio; }
        nsel = k + 1;
        if (ln_[0] == bn && lv[0] == bv){            // winner lane pops its head
            #pragma unroll
            for (int k2 = 0; k2 < 12; k2++){ lv[k2] = lv[k2+1]; ln_[k2] = ln_[k2+1]; lio[k2] = lio[k2+1]; }
            lv[12] = -1.0f; ln_[12] = 0x7fffffff; lio[12] = 0.0f;
        }
    }

    // parallel claims: lanes 0..nsel-1 each claim one selected anchor
    if (lane < nsel){
        int idx = b*Nc + myN;
        int old = atomicAdd(&g_fgm[idx], (1 << 20) | bm);
        if ((old >> 20) == 0){                       // first claim -> append once
            int p = atomicAdd(&g_npos, 1);
            g_plist[p] = idx;
        }
        g_al[idx]  = myV;                            // valid iff final count==1
        g_iou[idx] = myIo;
    }
}

// ---- K2: resolve + grid barrier + positive losses + final reduce ----
__global__ void __launch_bounds__(256) k_post(const float* __restrict__ cls,
                                              const float* __restrict__ raw,
                                              const int*   __restrict__ gtl,
                                              float* __restrict__ out){
    int tid = threadIdx.x;
    int i = blockIdx.x*256 + tid;
    int npos = g_npos;

    // phase R: resolve (no early return — grid barrier below)
    if (i < npos){
        int idx = g_plist[i];
        int b = idx / Nc;
        int fgm = g_fgm[idx];
        int m; float iou, al;
        if ((fgm >> 20) == 1){
            m   = fgm & 63;
            al  = g_al[idx];
            iou = g_iou[idx];
        } else {
            float4 p0 = g_dec[2*idx], p1 = g_dec[2*idx+1];
            float bv = -1.0f; int bm_ = 0;
            #pragma unroll 4
            for (int mm = 0; mm < 64; mm++){
                float4 q0 = g_gt[3*(b*64+mm)], q1 = g_gt[3*(b*64+mm)+1];
                float hd = probiou_hd(q0.x, q0.y, q0.z, q0.w, q1.x, q1.y,
                                      p0.x, p0.y, p0.z, p0.w, p1.x, p1.y);
                float io = fmaxf(1.0f - hd, 0.0f);
                if (io > bv){ bv = io; bm_ = mm; }   // first-max == jnp.argmax
            }
            m = bm_; iou = bv;
            int label = gtl[b*64 + m];
            float sg = fast_sig(cls[(size_t)idx*Cc + label]);
            float i2 = iou*iou;
            al = sg * i2*i2*i2;
            g_al[idx] = al;
        }
        g_m[idx] = m;
        atomicMax(&g_maxal [b*64 + m], __float_as_uint(al));
        atomicMax(&g_maxiou[b*64 + m], __float_as_uint(iou));
    }

    // software grid barrier (52 blocks, all co-resident)
    __threadfence();
    if (tid == 0){
        atomicAdd(&g_sync, 1);
        while (atomicAdd(&g_sync, 0) < POSBLK) {}
    }
    __syncthreads();

    // phase P: positive losses
    double dC = 0.0, dB = 0.0, dA = 0.0, dS = 0.0, dN = 0.0;
    if (i < npos){
        int idx = g_plist[i];
        int b = idx / Nc;
        int m = g_m[idx];
        int gi = b*64 + m;
        int label = gtl[gi];
        float ma = __uint_as_float(g_maxal [gi]);
        float mi = __uint_as_float(g_maxiou[gi]);
        float na = g_al[idx] * mi * __fdividef(1.0f, ma + EPSA);
        // cls correction: replace the negative-assumed label term with the true one
        float x  = cls[(size_t)idx*Cc + label];
        float em = __expf(-fabsf(x));
        float t  = 1.0f + em;
        float sp = fmaxf(x, 0.0f) + __logf(t);
        float sg = ((x >= 0.0f) ? 1.0f : em) * __fdividef(1.0f, t);
        dC = (double)((sp - x*na)*na - sp*0.75f*sg*sg);
        // box loss
        float4 p0 = g_dec[2*idx], p1 = g_dec[2*idx+1];
        float4 q0 = g_gt[3*gi], q1 = g_gt[3*gi+1], q2 = g_gt[3*gi+2];
        float hd = probiou_hd(p0.x, p0.y, p0.z, p0.w, p1.x, p1.y,
                              q0.x, q0.y, q0.z, q0.w, q1.x, q1.y);
        dB = (double)(hd * na);
        // angle CE
        float tA = q2.z / ANGLE_SCALE_F;
        tA = fminf(fmaxf(tA, 0.0f), 89.99f);
        int li = (int)tA;
        int ri = min(li + 1, 90);
        float lw = (float)ri - tA;
        float rw = 1.0f - lw;
        float lse = p1.z;
        const float* ra = raw + (size_t)idx*ABp;
        dA = (double)((lse - ra[li])*lw + (lse - ra[ri])*rw);
        dS = (double)na;
        dN = 1.0;
    }
    double vals[5] = {dC, dB, dA, dS, dN};
    #pragma unroll
    for (int k = 0; k < 5; k++){
        double v = block_red(vals[k]);
        if (tid == 0) g_ppart[blockIdx.x*5 + k] = v;
    }
    __threadfence();
    __shared__ int slast;
    if (tid == 0) slast = (atomicAdd(&g_done, 1) == POSBLK - 1) ? 1 : 0;
    __syncthreads();
    if (!slast) return;
    __threadfence();
    // final deterministic reduce
    double accC = 0.0;
    for (int j = tid; j < NEGBLK; j += 256) accC += g_negpart[j];
    double acc[5] = {0, 0, 0, 0, 0};
    for (int j = tid; j < POSBLK; j += 256){
        #pragma unroll
        for (int k = 0; k < 5; k++) acc[k] += g_ppart[j*5 + k];
    }
    __shared__ double fin[6];
    double v = block_red(accC);
    if (tid == 0) fin[0] = v;
    #pragma unroll
    for (int k = 0; k < 5; k++){
        v = block_red(acc[k]);
        if (tid == 0) fin[1 + k] = v;
    }
    __syncthreads();
    if (tid == 0){
        double ss   = fmax(fin[4], 1.0);             // score_sum
        double lcls = (fin[0] + fin[1]) / ss;        // neg sum + pos corrections
        double lbox = fin[2] / ss;
        double np_  = fmax(fin[5], 1.0);
        double lang = fin[3] / np_;
        out[0] = (float)(lcls + 2.5*lbox + 0.05*lang);
        out[1] = (float)lcls;
        out[2] = (float)lbox;
        out[3] = (float)lang;
    }
}

extern "C" void kernel_launch(void* const* d_in, const int* in_sizes, int n_in,
                              void* d_out, int out_size){
    const float* cls = (const float*)d_in[0];
    const float* reg = (const float*)d_in[1];
    const float* raw = (const float*)d_in[2];
    const int*   gtl = (const int*)  d_in[3];
    const float* gtb = (const float*)d_in[4];
    const float* vm  = (const float*)d_in[5];

    k_prep  <<<NEGBLK, 256>>>(cls, gtb);
    k_assign<<<Bc*Mc, 256>>>(cls, raw, reg, gtl, vm);
    k_post  <<<POSBLK, 256>>>(cls, raw, gtl, (float*)d_out);
}

// round 8
// speedup vs baseline: 1.3708x; 1.0376x over previous
#include <cuda_runtime.h>
#include <math.h>
#include <float.h>
#include <stdint.h>

// Problem constants (fixed by setup_inputs)
#define Bc 16
#define Nc 21504           // 128^2 + 64^2 + 32^2 anchors
#define Mc 64
#define Cc 15
#define ABp 91             // angle bins + 1
#define BNc (Bc*Nc)        // 344064
#define NEGBLK (BNc/256)   // 1344
#define POSBLK 52          // 52*256 = 13312 = max claims (1024 GT * 13)
#define CAND 768           // per-GT candidate bound (max in-box cells ~525)
#define EPSA 1e-9f
#define ANGLE_SCALE_F ((float)((3.14159265358979323846/2.0)/90.0))

// ---- device scratch (static; no allocations) ----
__device__ float4   g_dec[BNc*2];        // per anchor: {x,y,a,b},{c,det,lse,0} (candidates only)
__device__ int      g_fgm[BNc];          // (count<<20) | bm  (bm valid iff count==1)
__device__ int      g_m[BNc];
__device__ float    g_al[BNc];
__device__ float    g_iou[BNc];
__device__ float4   g_gt[Bc*Mc*3];       // per GT: {cx,cy,a,b},{c,det,hw,hh},{ca,sa,ang,0}
__device__ unsigned g_maxal[Bc*Mc], g_maxiou[Bc*Mc];
__device__ int      g_item[Bc*Mc*CAND];  // flat: (bm<<15)|n
__device__ float    g_sv [Bc*Mc*CAND];   // flat align values
__device__ float    g_sio[Bc*Mc*CAND];   // flat ious
__device__ int      g_cbase[Bc*Mc];
__device__ int      g_ccnt[Bc*Mc];
__device__ int      g_nitems;
__device__ int      g_npos;
__device__ int      g_done;
__device__ int      g_sync;
__device__ int      g_plist[16384];
__device__ double   g_negpart[NEGBLK];
__device__ double   g_ppart[POSBLK*5];

// ProbIoU Hellinger distance (eps=1e-3), fast transcendentals (err ~1e-6, budget 1e-3)
__device__ __forceinline__ float probiou_hd(float x1, float y1, float a1, float b1, float c1, float d1,
                                            float x2, float y2, float a2, float b2, float c2, float d2){
    float a = a1 + a2, b = b1 + b2, c = c1 + c2;
    float denom = a*b - c*c + 1e-3f;
    float dy = y1 - y2, dx = x1 - x2;
    float rd = __fdividef(1.0f, denom);
    float t1 = (a*dy*dy + b*dx*dx) * rd * 0.25f;
    float t2 = c * (-dx) * dy * rd * 0.5f;
    float t3 = 0.5f * __logf(denom * __fdividef(1.0f, 4.0f*sqrtf(d1*d2) + 1e-3f) + 1e-3f);
    float bd = fminf(fmaxf(t1 + t2 + t3, 1e-3f), 100.0f);
    return sqrtf(1.0f - __expf(-bd) + 1e-7f);
}

__device__ __forceinline__ float fast_sig(float x){
    return __fdividef(1.0f, 1.0f + __expf(-x));
}

// block reduction of a double over 256 threads; result valid on thread 0
__device__ __forceinline__ double block_red(double v){
    __shared__ double sred[8];
    #pragma unroll
    for (int o = 16; o; o >>= 1) v += __shfl_down_sync(0xffffffffu, v, o);
    int w = threadIdx.x >> 5, l = threadIdx.x & 31;
    if (l == 0) sred[w] = v;
    __syncthreads();
    if (w == 0){
        v = (l < 8) ? sred[l] : 0.0;
        #pragma unroll
        for (int o = 4; o; o >>= 1) v += __shfl_down_sync(0xffffffffu, v, o);
    }
    __syncthreads();
    return v;
}

// ---- K0: counters + g_fgm memset + GT prep + classless negative focal BCE ----
__global__ void k_prep(const float* __restrict__ cls, const float* __restrict__ gtb){
    int i = blockIdx.x*256 + threadIdx.x;
    g_fgm[i] = 0;
    if (i == 0){ g_npos = 0; g_done = 0; g_sync = 0; g_nitems = 0; }
    if (i < Bc*Mc){
        const float* g = gtb + i*5;
        float cx = g[0], cy = g[1], w = g[2], h = g[3], an = g[4];
        float ca = __cosf(an), sa = __sinf(an);
        float A = w*w/12.0f, B = h*h/12.0f;
        float ga = A*ca*ca + B*sa*sa;
        float gb = A*sa*sa + B*ca*ca;
        float gc = (A - B)*ca*sa;
        float gd = fmaxf(ga*gb - gc*gc, 0.0f);
        g_gt[i*3+0] = make_float4(cx, cy, ga, gb);
        g_gt[i*3+1] = make_float4(gc, gd, w*0.5f, h*0.5f);
        g_gt[i*3+2] = make_float4(ca, sa, an, 0.0f);
        g_maxal[i] = 0u; g_maxiou[i] = 0u;
    }
    // classless negative focal BCE: sum over ALL logits, straight float4 stream
    const float4* src = (const float4*)cls;
    const int N4 = BNc*Cc/4;                  // 1290240
    float acc = 0.0f;
    for (int j = i; j < N4; j += NEGBLK*256){
        float4 v4 = src[j];
        #pragma unroll
        for (int c = 0; c < 4; c++){
            float x = (c==0)?v4.x:(c==1)?v4.y:(c==2)?v4.z:v4.w;
            float em = __expf(-fabsf(x));
            float t  = 1.0f + em;
            float sp = fmaxf(x, 0.0f) + __logf(t);       // softplus(x) = bce(x, t=0)
            float sg = ((x >= 0.0f) ? 1.0f : em) * __fdividef(1.0f, t);
            acc += 0.75f * sg * sg * sp;
        }
    }
    double v = block_red((double)acc);
    if (threadIdx.x == 0) g_negpart[blockIdx.x] = v;
}

// ---- K1: warp-per-GT: ballot-compact in-box candidates into flat item list ----
__global__ void __launch_bounds__(128) k_gather(const int* __restrict__ gtl,
                                                const float* __restrict__ vm){
    int w    = threadIdx.x >> 5;
    int lane = threadIdx.x & 31;
    int bm   = blockIdx.x*4 + w;
    if (vm[bm] == 0.0f){
        if (lane == 0){ g_ccnt[bm] = 0; }
        return;
    }
    float4 q1 = g_gt[3*bm+1], q2 = g_gt[3*bm+2];
    float4 q0 = g_gt[3*bm];
    float gcx = q0.x, gcy = q0.y;
    float hw = q1.z, hh = q1.w;
    float ca = q2.x, sa = q2.y;
    float hx = hw*ca + hh*sa;   // AABB half extents (ca,sa >= 0 for ang in [0,pi/2))
    float hy = hw*sa + hh*ca;

    int rng[3][4];   // per level: ix0, nx, iy0, tot
    int count = 0;
    #pragma unroll
    for (int L = 0; L < 3; L++){
        float st  = (L == 0) ? 8.0f : (L == 1) ? 16.0f : 32.0f;
        int npl   = (L == 0) ? 128  : (L == 1) ? 64   : 32;
        float is  = __fdividef(1.0f, st);
        int ix0 = max(0,     (int)((gcx - hx)*is - 0.5f) - 1);
        int ix1 = min(npl-1, (int)((gcx + hx)*is - 0.5f) + 1);
        int iy0 = max(0,     (int)((gcy - hy)*is - 0.5f) - 1);
        int iy1 = min(npl-1, (int)((gcy + hy)*is - 0.5f) + 1);
        int nx = ix1 - ix0 + 1, ny = iy1 - iy0 + 1;
        int tot = (nx > 0 && ny > 0) ? nx*ny : 0;
        rng[L][0] = ix0; rng[L][1] = nx; rng[L][2] = iy0; rng[L][3] = tot;
        int npl_ = npl; float st_ = st;
        for (int j0 = 0; j0 < tot; j0 += 32){
            int j = j0 + lane;
            bool in = false;
            if (j < tot){
                int ix = ix0 + j % nx, iy = iy0 + j / nx;
                float ax = (ix + 0.5f)*st_, ay = (iy + 0.5f)*st_;
                float dx = ax - gcx, dy = ay - gcy;
                float xr = dx*ca + dy*sa;
                float yr = dy*ca - dx*sa;
                in = (fabsf(xr) < hw) && (fabsf(yr) < hh);
            }
            count += __popc(__ballot_sync(0xffffffffu, in));
        }
        (void)npl_;
    }
    int base = 0;
    if (lane == 0) base = atomicAdd(&g_nitems, count);
    base = __shfl_sync(0xffffffffu, base, 0);
    if (lane == 0){ g_cbase[bm] = base; g_ccnt[bm] = count; }

    // pass 2: compact write
    int off = 0;
    #pragma unroll
    for (int L = 0; L < 3; L++){
        float st  = (L == 0) ? 8.0f : (L == 1) ? 16.0f : 32.0f;
        int npl   = (L == 0) ? 128  : (L == 1) ? 64   : 32;
        int baseN = (L == 0) ? 0    : (L == 1) ? 16384 : 20480;
        int ix0 = rng[L][0], nx = rng[L][1], iy0 = rng[L][2], tot = rng[L][3];
        for (int j0 = 0; j0 < tot; j0 += 32){
            int j = j0 + lane;
            bool in = false; int n = 0;
            if (j < tot){
                int ix = ix0 + j % nx, iy = iy0 + j / nx;
                float ax = (ix + 0.5f)*st, ay = (iy + 0.5f)*st;
                float dx = ax - gcx, dy = ay - gcy;
                float xr = dx*ca + dy*sa;
                float yr = dy*ca - dx*sa;
                in = (fabsf(xr) < hw) && (fabsf(yr) < hh);
                n = baseN + iy*npl + ix;
            }
            unsigned mask = __ballot_sync(0xffffffffu, in);
            if (in){
                int pos = base + off + __popc(mask & ((1u << lane) - 1u));
                g_item[pos] = (bm << 15) | n;
            }
            off += __popc(mask);
        }
    }
}

// ---- K2: flat grid-stride work: 8 lanes per item, decode + probiou + align ----
__global__ void __launch_bounds__(256) k_work(const float* __restrict__ cls,
                                              const float* __restrict__ raw,
                                              const float* __restrict__ reg,
                                              const int*   __restrict__ gtl){
    int nit = g_nitems;
    int t8  = threadIdx.x & 7;
    int gid = (blockIdx.x*blockDim.x + threadIdx.x) >> 3;
    int ng  = (gridDim.x*blockDim.x) >> 3;
    for (int i = gid; i < nit; i += ng){
        int it = g_item[i];
        int bm = it >> 15, n = it & 0x7fff;
        int b  = bm >> 6;
        int idx = b*Nc + n;
        const float* rr = raw + (size_t)idx*ABp;
        float s = 0.0f, wk = 0.0f;
        #pragma unroll
        for (int k2 = 0; k2 < 12; k2++){
            int kk = t8 + (k2 << 3);
            if (kk < ABp){
                float e = __expf(rr[kk]);
                s += e;
                wk = fmaf((float)kk, e, wk);
            }
        }
        #pragma unroll
        for (int o = 1; o < 8; o <<= 1){
            s  += __shfl_xor_sync(0xffffffffu, s,  o);
            wk += __shfl_xor_sync(0xffffffffu, wk, o);
        }
        if (t8 == 0){
            float ang = __fdividef(wk, s) * ANGLE_SCALE_F;
            float lse = __logf(s);
            float4 rd = *(const float4*)(reg + (size_t)idx*4);
            float offx = (rd.z - rd.x)*0.5f, offy = (rd.w - rd.y)*0.5f;
            float c = __cosf(ang), sn = __sinf(ang);
            float ax, ay, st;
            if (n < 16384)      { int ii = n;         ax = ((ii & 127) + 0.5f)*8.0f;  ay = ((ii >> 7) + 0.5f)*8.0f;  st = 8.0f;  }
            else if (n < 20480) { int ii = n - 16384; ax = ((ii &  63) + 0.5f)*16.0f; ay = ((ii >> 6) + 0.5f)*16.0f; st = 16.0f; }
            else                { int ii = n - 20480; ax = ((ii &  31) + 0.5f)*32.0f; ay = ((ii >> 5) + 0.5f)*32.0f; st = 32.0f; }
            float X = (offx*c - offy*sn)*st + ax;
            float Y = (offx*sn + offy*c)*st + ay;
            float W = (rd.x + rd.z)*st, H = (rd.y + rd.w)*st;
            float A = W*W/12.0f, Bv = H*H/12.0f;
            float pa = A*c*c + Bv*sn*sn;
            float pb = A*sn*sn + Bv*c*c;
            float pc = (A - Bv)*c*sn;
            float pd = fmaxf(pa*pb - pc*pc, 0.0f);
            g_dec[2*idx]   = make_float4(X, Y, pa, pb);   // duplicate writes across GTs: identical
            g_dec[2*idx+1] = make_float4(pc, pd, lse, 0.0f);
            float4 q0 = g_gt[3*bm], q1 = g_gt[3*bm+1];
            float hd = probiou_hd(q0.x, q0.y, q0.z, q0.w, q1.x, q1.y,
                                  X, Y, pa, pb, pc, pd);
            float iou = fmaxf(1.0f - hd, 0.0f);
            float sg = fast_sig(cls[(size_t)idx*Cc + gtl[bm]]);
            float i2 = iou*iou;
            g_sv[i]  = sg * i2*i2*i2;               // score^1 * iou^6
            g_sio[i] = iou;
        }
    }
}

// ---- K3: warp-per-GT: register top-13 over flat segment + parallel claims ----
__global__ void __launch_bounds__(128) k_select(void){
    int w    = threadIdx.x >> 5;
    int lane = threadIdx.x & 31;
    int bm   = blockIdx.x*4 + w;
    int count = g_ccnt[bm];
    if (count == 0) return;
    int base = g_cbase[bm];
    int b    = bm >> 6;

    // per-lane register top-13 (desc value, asc index tiebreak == lax.top_k)
    float lv[13]; int ln_[13]; float lio[13];
    #pragma unroll
    for (int k = 0; k < 13; k++){ lv[k] = -1.0f; ln_[k] = 0x7fffffff; lio[k] = 0.0f; }
    for (int j = lane; j < count; j += 32){
        float v = g_sv[base + j];
        if (v <= EPSA) continue;                     // valid = topv > EPS
        int n = g_item[base + j] & 0x7fff;
        float io = g_sio[base + j];
        if (v > lv[12] || (v == lv[12] && n < ln_[12])){
            lv[12] = v; ln_[12] = n; lio[12] = io;
            #pragma unroll
            for (int k = 12; k > 0; k--){
                bool sw = (lv[k] > lv[k-1]) || (lv[k] == lv[k-1] && ln_[k] < ln_[k-1]);
                if (sw){
                    float tv = lv[k-1];  lv[k-1]  = lv[k];  lv[k]  = tv;
                    int   tn = ln_[k-1]; ln_[k-1] = ln_[k]; ln_[k] = tn;
                    float ti = lio[k-1]; lio[k-1] = lio[k]; lio[k] = ti;
                }
            }
        }
    }

    // 13 butterfly merge rounds; winner k distributed to lane k
    float myV = -1.0f; int myN = 0; float myIo = 0.0f;
    int nsel = 0;
    for (int k = 0; k < 13; k++){
        float bv = lv[0]; int bn = ln_[0]; float bio = lio[0];
        #pragma unroll
        for (int o = 16; o; o >>= 1){
            float ov = __shfl_xor_sync(0xffffffffu, bv, o);
            int   on = __shfl_xor_sync(0xffffffffu, bn, o);
            float oo = __shfl_xor_sync(0xffffffffu, bio, o);
            if (ov > bv || (ov == bv && on < bn)){ bv = ov; bn = on; bio = oo; }
        }
        if (bv <= EPSA) break;
        if (lane == k){ myV = bv; myN = bn; myIo = bio; }
        nsel = k + 1;
        if (ln_[0] == bn && lv[0] == bv){            // winner lane pops its head
            #pragma unroll
            for (int k2 = 0; k2 < 12; k2++){ lv[k2] = lv[k2+1]; ln_[k2] = ln_[k2+1]; lio[k2] = lio[k2+1]; }
            lv[12] = -1.0f; ln_[12] = 0x7fffffff; lio[12] = 0.0f;
        }
    }

    // parallel claims: lanes 0..nsel-1 each claim one selected anchor
    if (lane < nsel){
        int idx = b*Nc + myN;
        int old = atomicAdd(&g_fgm[idx], (1 << 20) | bm);
        if ((old >> 20) == 0){                       // first claim -> append once
            int p = atomicAdd(&g_npos, 1);
            g_plist[p] = idx;
        }
        g_al[idx]  = myV;                            // valid iff final count==1
        g_iou[idx] = myIo;
    }
}

// ---- K4: resolve + grid barrier + positive losses + final reduce ----
__global__ void __launch_bounds__(256) k_post(const float* __restrict__ cls,
                                              const float* __restrict__ raw,
                                              const int*   __restrict__ gtl,
                                              float* __restrict__ out){
    int tid = threadIdx.x;
    int i = blockIdx.x*256 + tid;
    int npos = g_npos;

    // phase R: resolve (no early return — grid barrier below)
    if (i < npos){
        int idx = g_plist[i];
        int b = idx / Nc;
        int fgm = g_fgm[idx];
        int m; float iou, al;
        if ((fgm >> 20) == 1){
            m   = fgm & 63;
            al  = g_al[idx];
            iou = g_iou[idx];
        } else {
            float4 p0 = g_dec[2*idx], p1 = g_dec[2*idx+1];
            float bv = -1.0f; int bm_ = 0;
            #pragma unroll 4
            for (int mm = 0; mm < 64; mm++){
                float4 q0 = g_gt[3*(b*64+mm)], q1 = g_gt[3*(b*64+mm)+1];
                float hd = probiou_hd(q0.x, q0.y, q0.z, q0.w, q1.x, q1.y,
                                      p0.x, p0.y, p0.z, p0.w, p1.x, p1.y);
                float io = fmaxf(1.0f - hd, 0.0f);
                if (io > bv){ bv = io; bm_ = mm; }   // first-max == jnp.argmax
            }
            m = bm_; iou = bv;
            int label = gtl[b*64 + m];
            float sg = fast_sig(cls[(size_t)idx*Cc + label]);
            float i2 = iou*iou;
            al = sg * i2*i2*i2;
            g_al[idx] = al;
        }
        g_m[idx] = m;
        atomicMax(&g_maxal [b*64 + m], __float_as_uint(al));
        atomicMax(&g_maxiou[b*64 + m], __float_as_uint(iou));
    }

    // software grid barrier (52 blocks, all co-resident)
    __threadfence();
    if (tid == 0){
        atomicAdd(&g_sync, 1);
        while (atomicAdd(&g_sync, 0) < POSBLK) {}
    }
    __syncthreads();

    // phase P: positive losses
    double dC = 0.0, dB = 0.0, dA = 0.0, dS = 0.0, dN = 0.0;
    if (i < npos){
        int idx = g_plist[i];
        int b = idx / Nc;
        int m = g_m[idx];
        int gi = b*64 + m;
        int label = gtl[gi];
        float ma = __uint_as_float(g_maxal [gi]);
        float mi = __uint_as_float(g_maxiou[gi]);
        float na = g_al[idx] * mi * __fdividef(1.0f, ma + EPSA);
        // cls correction: replace the negative-assumed label term with the true one
        float x  = cls[(size_t)idx*Cc + label];
        float em = __expf(-fabsf(x));
        float t  = 1.0f + em;
        float sp = fmaxf(x, 0.0f) + __logf(t);
        float sg = ((x >= 0.0f) ? 1.0f : em) * __fdividef(1.0f, t);
        dC = (double)((sp - x*na)*na - sp*0.75f*sg*sg);
        // box loss
        float4 p0 = g_dec[2*idx], p1 = g_dec[2*idx+1];
        float4 q0 = g_gt[3*gi], q1 = g_gt[3*gi+1], q2 = g_gt[3*gi+2];
        float hd = probiou_hd(p0.x, p0.y, p0.z, p0.w, p1.x, p1.y,
                              q0.x, q0.y, q0.z, q0.w, q1.x, q1.y);
        dB = (double)(hd * na);
        // angle CE
        float tA = q2.z / ANGLE_SCALE_F;
        tA = fminf(fmaxf(tA, 0.0f), 89.99f);
        int li = (int)tA;
        int ri = min(li + 1, 90);
        float lw = (float)ri - tA;
        float rw = 1.0f - lw;
        float lse = p1.z;
        const float* ra = raw + (size_t)idx*ABp;
        dA = (double)((lse - ra[li])*lw + (lse - ra[ri])*rw);
        dS = (double)na;
        dN = 1.0;
    }
    double vals[5] = {dC, dB, dA, dS, dN};
    #pragma unroll
    for (int k = 0; k < 5; k++){
        double v = block_red(vals[k]);
        if (tid == 0) g_ppart[blockIdx.x*5 + k] = v;
    }
    __threadfence();
    __shared__ int slast;
    if (tid == 0) slast = (atomicAdd(&g_done, 1) == POSBLK - 1) ? 1 : 0;
    __syncthreads();
    if (!slast) return;
    __threadfence();
    // final deterministic reduce
    double accC = 0.0;
    for (int j = tid; j < NEGBLK; j += 256) accC += g_negpart[j];
    double acc[5] = {0, 0, 0, 0, 0};
    for (int j = tid; j < POSBLK; j += 256){
        #pragma unroll
        for (int k = 0; k < 5; k++) acc[k] += g_ppart[j*5 + k];
    }
    __shared__ double fin[6];
    double v = block_red(accC);
    if (tid == 0) fin[0] = v;
    #pragma unroll
    for (int k = 0; k < 5; k++){
        v = block_red(acc[k]);
        if (tid == 0) fin[1 + k] = v;
    }
    __syncthreads();
    if (tid == 0){
        double ss   = fmax(fin[4], 1.0);             // score_sum
        double lcls = (fin[0] + fin[1]) / ss;        // neg sum + pos corrections
        double lbox = fin[2] / ss;
        double np_  = fmax(fin[5], 1.0);
        double lang = fin[3] / np_;
        out[0] = (float)(lcls + 2.5*lbox + 0.05*lang);
        out[1] = (float)lcls;
        out[2] = (float)lbox;
        out[3] = (float)lang;
    }
}

extern "C" void kernel_launch(void* const* d_in, const int* in_sizes, int n_in,
                              void* d_out, int out_size){
    const float* cls = (const float*)d_in[0];
    const float* reg = (const float*)d_in[1];
    const float* raw = (const float*)d_in[2];
    const int*   gtl = (const int*)  d_in[3];
    const float* gtb = (const float*)d_in[4];
    const float* vm  = (const float*)d_in[5];

    k_prep  <<<NEGBLK, 256>>>(cls, gtb);
    k_gather<<<Bc*Mc/4, 128>>>(gtl, vm);
    k_work  <<<1024, 256>>>(cls, raw, reg, gtl);
    k_select<<<Bc*Mc/4, 128>>>();
    k_post  <<<POSBLK, 256>>>(cls, raw, gtl, (float*)d_out);
}

// round 10
// speedup vs baseline: 1.3729x; 1.0015x over previous
#include <cuda_runtime.h>
#include <math.h>
#include <float.h>
#include <stdint.h>

// Problem constants (fixed by setup_inputs)
#define Bc 16
#define Nc 21504           // 128^2 + 64^2 + 32^2 anchors
#define Mc 64
#define Cc 15
#define ABp 91             // angle bins + 1
#define BNc (Bc*Nc)        // 344064
#define PREPBLK (BNc/256)  // 1344 (blocks 0..127 gather, 128..1343 BCE)
#define GATHBLK 128
#define NEGP (PREPBLK-GATHBLK)   // 1216 BCE partials
#define POSBLK 52          // 52*256 = 13312 = max claims (1024 GT * 13)
#define CAND 768           // per-GT candidate bound (max in-box cells ~525)
#define EPSA 1e-9f
#define ANGLE_SCALE_F ((float)((3.14159265358979323846/2.0)/90.0))

// ---- device scratch (static; no allocations) ----
__device__ float4   g_dec[BNc*2];        // per anchor: {x,y,a,b},{c,det,lse,0} (candidates only)
__device__ int      g_fgm[BNc];          // (count<<20) | bm  (bm valid iff count==1)
__device__ int      g_m[BNc];
__device__ float    g_al[BNc];
__device__ float    g_iou[BNc];
__device__ float4   g_gt[Bc*Mc*3];       // per GT: {cx,cy,a,b},{c,det,hw,hh},{ca,sa,ang,0}
__device__ unsigned g_maxal[Bc*Mc], g_maxiou[Bc*Mc];
__device__ int      g_item[Bc*Mc*CAND];  // flat: (bm<<15)|n  (n ascending within segment)
__device__ float    g_sv [Bc*Mc*CAND];   // flat align values
__device__ float    g_sio[Bc*Mc*CAND];   // flat ious
__device__ int      g_cbase[Bc*Mc];
__device__ int      g_ccnt[Bc*Mc];
__device__ int      g_nitems = 0;        // static-zero; reset at end of k_post
__device__ int      g_npos   = 0;
__device__ int      g_done   = 0;
__device__ int      g_sync   = 0;
__device__ int      g_plist[16384];
__device__ double   g_negpart[NEGP];
__device__ double   g_ppart[POSBLK*5];

// ProbIoU Hellinger distance (eps=1e-3), fast transcendentals (err ~1e-6, budget 1e-3)
__device__ __forceinline__ float probiou_hd(float x1, float y1, float a1, float b1, float c1, float d1,
                                            float x2, float y2, float a2, float b2, float c2, float d2){
    float a = a1 + a2, b = b1 + b2, c = c1 + c2;
    float denom = a*b - c*c + 1e-3f;
    float dy = y1 - y2, dx = x1 - x2;
    float rd = __fdividef(1.0f, denom);
    float t1 = (a*dy*dy + b*dx*dx) * rd * 0.25f;
    float t2 = c * (-dx) * dy * rd * 0.5f;
    float t3 = 0.5f * __logf(denom * __fdividef(1.0f, 4.0f*sqrtf(d1*d2) + 1e-3f) + 1e-3f);
    float bd = fminf(fmaxf(t1 + t2 + t3, 1e-3f), 100.0f);
    return sqrtf(1.0f - __expf(-bd) + 1e-7f);
}

__device__ __forceinline__ float fast_sig(float x){
    return __fdividef(1.0f, 1.0f + __expf(-x));
}

// block reduction of a double over 256 threads; result valid on thread 0
__device__ __forceinline__ double block_red(double v){
    __shared__ double sred[8];
    #pragma unroll
    for (int o = 16; o; o >>= 1) v += __shfl_down_sync(0xffffffffu, v, o);
    int w = threadIdx.x >> 5, l = threadIdx.x & 31;
    if (l == 0) sred[w] = v;
    __syncthreads();
    if (w == 0){
        v = (l < 8) ? sred[l] : 0.0;
        #pragma unroll
        for (int o = 4; o; o >>= 1) v += __shfl_down_sync(0xffffffffu, v, o);
    }
    __syncthreads();
    return v;
}

// ---- K0: g_fgm memset + [blocks 0..127: GT prep + gather] + [blocks 128..: negative BCE] ----
__global__ void __launch_bounds__(256) k_prep(const float* __restrict__ cls,
                                              const float* __restrict__ gtb,
                                              const float* __restrict__ vm){
    int tid = threadIdx.x;
    int i = blockIdx.x*256 + tid;
    g_fgm[i] = 0;

    if (blockIdx.x < GATHBLK){
        // gather path: 8 warps, one GT each
        int w    = tid >> 5;
        int lane = tid & 31;
        int bm   = blockIdx.x*8 + w;
        const float* g = gtb + bm*5;
        float gcx = g[0], gcy = g[1], gw_ = g[2], gh_ = g[3], gang = g[4];
        float ca = __cosf(gang), sa = __sinf(gang);
        float A = gw_*gw_/12.0f, B = gh_*gh_/12.0f;
        float ga = A*ca*ca + B*sa*sa;
        float gb = A*sa*sa + B*ca*ca;
        float gc = (A - B)*ca*sa;
        float gd = fmaxf(ga*gb - gc*gc, 0.0f);
        float hw = gw_*0.5f, hh = gh_*0.5f;
        if (lane == 0){
            g_gt[bm*3+0] = make_float4(gcx, gcy, ga, gb);
            g_gt[bm*3+1] = make_float4(gc, gd, hw, hh);
            g_gt[bm*3+2] = make_float4(ca, sa, gang, 0.0f);
            g_maxal[bm] = 0u; g_maxiou[bm] = 0u;
        }
        if (vm[bm] == 0.0f){
            if (lane == 0) g_ccnt[bm] = 0;
            return;
        }
        float hx = hw*ca + hh*sa;   // AABB half extents (ca,sa >= 0 for ang in [0,pi/2))
        float hy = hw*sa + hh*ca;

        int rng[3][4];   // per level: ix0, nx, iy0, tot
        int count = 0;
        #pragma unroll
        for (int L = 0; L < 3; L++){
            float st  = (L == 0) ? 8.0f : (L == 1) ? 16.0f : 32.0f;
            int npl   = (L == 0) ? 128  : (L == 1) ? 64   : 32;
            float is  = __fdividef(1.0f, st);
            int ix0 = max(0,     (int)((gcx - hx)*is - 0.5f) - 1);
            int ix1 = min(npl-1, (int)((gcx + hx)*is - 0.5f) + 1);
            int iy0 = max(0,     (int)((gcy - hy)*is - 0.5f) - 1);
            int iy1 = min(npl-1, (int)((gcy + hy)*is - 0.5f) + 1);
            int nx = ix1 - ix0 + 1, ny = iy1 - iy0 + 1;
            int tot = (nx > 0 && ny > 0) ? nx*ny : 0;
            rng[L][0] = ix0; rng[L][1] = nx; rng[L][2] = iy0; rng[L][3] = tot;
            for (int j0 = 0; j0 < tot; j0 += 32){
                int j = j0 + lane;
                bool in = false;
                if (j < tot){
                    int ix = ix0 + j % nx, iy = iy0 + j / nx;
                    float ax = (ix + 0.5f)*st, ay = (iy + 0.5f)*st;
                    float dx = ax - gcx, dy = ay - gcy;
                    float xr = dx*ca + dy*sa;
                    float yr = dy*ca - dx*sa;
                    in = (fabsf(xr) < hw) && (fabsf(yr) < hh);
                }
                count += __popc(__ballot_sync(0xffffffffu, in));
            }
        }
        int base = 0;
        if (lane == 0) base = atomicAdd(&g_nitems, count);
        base = __shfl_sync(0xffffffffu, base, 0);
        if (lane == 0){ g_cbase[bm] = base; g_ccnt[bm] = count; }

        // pass 2: compact write (n ascending within segment)
        int off = 0;
        #pragma unroll
        for (int L = 0; L < 3; L++){
            float st  = (L == 0) ? 8.0f : (L == 1) ? 16.0f : 32.0f;
            int npl   = (L == 0) ? 128  : (L == 1) ? 64   : 32;
            int baseN = (L == 0) ? 0    : (L == 1) ? 16384 : 20480;
            int ix0 = rng[L][0], nx = rng[L][1], iy0 = rng[L][2], tot = rng[L][3];
            for (int j0 = 0; j0 < tot; j0 += 32){
                int j = j0 + lane;
                bool in = false; int n = 0;
                if (j < tot){
                    int ix = ix0 + j % nx, iy = iy0 + j / nx;
                    float ax = (ix + 0.5f)*st, ay = (iy + 0.5f)*st;
                    float dx = ax - gcx, dy = ay - gcy;
                    float xr = dx*ca + dy*sa;
                    float yr = dy*ca - dx*sa;
                    in = (fabsf(xr) < hw) && (fabsf(yr) < hh);
                    n = baseN + iy*npl + ix;
                }
                unsigned mask = __ballot_sync(0xffffffffu, in);
                if (in){
                    int pos = base + off + __popc(mask & ((1u << lane) - 1u));
                    g_item[pos] = (bm << 15) | n;
                }
                off += __popc(mask);
            }
        }
        return;
    }

    // BCE path: classless negative focal BCE over all logits, float4 stream
    const float4* src = (const float4*)cls;
    const int N4 = BNc*Cc/4;                  // 1290240
    int bce = blockIdx.x - GATHBLK;
    float acc = 0.0f;
    for (int j = bce*256 + tid; j < N4; j += NEGP*256){
        float4 v4 = src[j];
        #pragma unroll
        for (int c = 0; c < 4; c++){
            float x = (c==0)?v4.x:(c==1)?v4.y:(c==2)?v4.z:v4.w;
            float em = __expf(-fabsf(x));
            float t  = 1.0f + em;
            float sp = fmaxf(x, 0.0f) + __logf(t);       // softplus(x) = bce(x, t=0)
            float sg = ((x >= 0.0f) ? 1.0f : em) * __fdividef(1.0f, t);
            acc += 0.75f * sg * sg * sp;
        }
    }
    double v = block_red((double)acc);
    if (tid == 0) g_negpart[bce] = v;
}

// ---- K1: flat grid-stride work: 8 lanes per item, decode + probiou + align ----
__global__ void __launch_bounds__(256) k_work(const float* __restrict__ cls,
                                              const float* __restrict__ raw,
                                              const float* __restrict__ reg,
                                              const int*   __restrict__ gtl){
    int nit = g_nitems;
    int t8  = threadIdx.x & 7;
    int gid = (blockIdx.x*blockDim.x + threadIdx.x) >> 3;
    int ng  = (gridDim.x*blockDim.x) >> 3;
    for (int i = gid; i < nit; i += ng){
        int it = g_item[i];
        int bm = it >> 15, n = it & 0x7fff;
        int b  = bm >> 6;
        int idx = b*Nc + n;
        const float* rr = raw + (size_t)idx*ABp;
        float s = 0.0f, wk = 0.0f;
        #pragma unroll
        for (int k2 = 0; k2 < 12; k2++){
            int kk = t8 + (k2 << 3);
            if (kk < ABp){
                float e = __expf(rr[kk]);
                s += e;
                wk = fmaf((float)kk, e, wk);
            }
        }
        #pragma unroll
        for (int o = 1; o < 8; o <<= 1){
            s  += __shfl_xor_sync(0xffffffffu, s,  o);
            wk += __shfl_xor_sync(0xffffffffu, wk, o);
        }
        if (t8 == 0){
            float ang = __fdividef(wk, s) * ANGLE_SCALE_F;
            float lse = __logf(s);
            float4 rd = *(const float4*)(reg + (size_t)idx*4);
            float offx = (rd.z - rd.x)*0.5f, offy = (rd.w - rd.y)*0.5f;
            float c = __cosf(ang), sn = __sinf(ang);
            float ax, ay, st;
            if (n < 16384)      { int ii = n;         ax = ((ii & 127) + 0.5f)*8.0f;  ay = ((ii >> 7) + 0.5f)*8.0f;  st = 8.0f;  }
            else if (n < 20480) { int ii = n - 16384; ax = ((ii &  63) + 0.5f)*16.0f; ay = ((ii >> 6) + 0.5f)*16.0f; st = 16.0f; }
            else                { int ii = n - 20480; ax = ((ii &  31) + 0.5f)*32.0f; ay = ((ii >> 5) + 0.5f)*32.0f; st = 32.0f; }
            float X = (offx*c - offy*sn)*st + ax;
            float Y = (offx*sn + offy*c)*st + ay;
            float W = (rd.x + rd.z)*st, H = (rd.y + rd.w)*st;
            float A = W*W/12.0f, Bv = H*H/12.0f;
            float pa = A*c*c + Bv*sn*sn;
            float pb = A*sn*sn + Bv*c*c;
            float pc = (A - Bv)*c*sn;
            float pd = fmaxf(pa*pb - pc*pc, 0.0f);
            g_dec[2*idx]   = make_float4(X, Y, pa, pb);   // duplicate writes across GTs: identical
            g_dec[2*idx+1] = make_float4(pc, pd, lse, 0.0f);
            float4 q0 = g_gt[3*bm], q1 = g_gt[3*bm+1];
            float hd = probiou_hd(q0.x, q0.y, q0.z, q0.w, q1.x, q1.y,
                                  X, Y, pa, pb, pc, pd);
            float iou = fmaxf(1.0f - hd, 0.0f);
            float sg = fast_sig(cls[(size_t)idx*Cc + gtl[bm]]);
            float i2 = iou*iou;
            g_sv[i]  = sg * i2*i2*i2;               // score^1 * iou^6
            g_sio[i] = iou;
        }
    }
}

// ---- K2: rank test, one thread per item: selected iff < 13 items beat it; claim in place ----
__global__ void __launch_bounds__(256) k_rank(void){
    int nit = g_nitems;
    int gid = blockIdx.x*blockDim.x + threadIdx.x;
    int ng  = gridDim.x*blockDim.x;
    for (int i = gid; i < nit; i += ng){
        float v = g_sv[i];
        if (v <= EPSA) continue;                     // valid = topv > EPS
        int it = g_item[i];
        int bm = it >> 15;
        int base = g_cbase[bm];
        int count = g_ccnt[bm];
        int pos = i - base;
        const float* sv = g_sv + base;
        int beats = 0;
        int jc = 0;
        while (jc < count){
            int lim = min(jc + 16, count);
            for (int j = jc; j < lim; j++){
                float vj = __ldg(sv + j);
                beats += (vj > v || (vj == v && j < pos)) ? 1 : 0;
            }
            jc = lim;
            if (beats >= 13) break;
        }
        if (beats < 13){
            int n = it & 0x7fff;
            int b = bm >> 6;
            int idx = b*Nc + n;
            int old = atomicAdd(&g_fgm[idx], (1 << 20) | bm);
            if ((old >> 20) == 0){                   // first claim -> append once
                int p = atomicAdd(&g_npos, 1);
                g_plist[p] = idx;
            }
            g_al[idx]  = v;                          // valid iff final count==1
            g_iou[idx] = g_sio[i];
        }
    }
}

// ---- K3: resolve + grid barrier + positive losses + final reduce + counter reset ----
__global__ void __launch_bounds__(256) k_post(const float* __restrict__ cls,
                                              const float* __restrict__ raw,
                                              const int*   __restrict__ gtl,
                                              float* __restrict__ out){
    int tid = threadIdx.x;
    int i = blockIdx.x*256 + tid;
    int npos = g_npos;

    // phase R: resolve (no early return — grid barrier below)
    if (i < npos){
        int idx = g_plist[i];
        int b = idx / Nc;
        int fgm = g_fgm[idx];
        int m; float iou, al;
        if ((fgm >> 20) == 1){
            m   = fgm & 63;
            al  = g_al[idx];
            iou = g_iou[idx];
        } else {
            float4 p0 = g_dec[2*idx], p1 = g_dec[2*idx+1];
            float bv = -1.0f; int bm_ = 0;
            #pragma unroll 4
            for (int mm = 0; mm < 64; mm++){
                float4 q0 = g_gt[3*(b*64+mm)], q1 = g_gt[3*(b*64+mm)+1];
                float hd = probiou_hd(q0.x, q0.y, q0.z, q0.w, q1.x, q1.y,
                                      p0.x, p0.y, p0.z, p0.w, p1.x, p1.y);
                float io = fmaxf(1.0f - hd, 0.0f);
                if (io > bv){ bv = io; bm_ = mm; }   // first-max == jnp.argmax
            }
            m = bm_; iou = bv;
            int label = gtl[b*64 + m];
            float sg = fast_sig(cls[(size_t)idx*Cc + label]);
            float i2 = iou*iou;
            al = sg * i2*i2*i2;
            g_al[idx] = al;
        }
        g_m[idx] = m;
        atomicMax(&g_maxal [b*64 + m], __float_as_uint(al));
        atomicMax(&g_maxiou[b*64 + m], __float_as_uint(iou));
    }

    // software grid barrier (52 blocks, all co-resident)
    __threadfence();
    if (tid == 0){
        atomicAdd(&g_sync, 1);
        while (atomicAdd(&g_sync, 0) < POSBLK) {}
    }
    __syncthreads();

    // phase P: positive losses
    double dC = 0.0, dB = 0.0, dA = 0.0, dS = 0.0, dN = 0.0;
    if (i < npos){
        int idx = g_plist[i];
        int b = idx / Nc;
        int m = g_m[idx];
        int gi = b*64 + m;
        int label = gtl[gi];
        float ma = __uint_as_float(g_maxal [gi]);
        float mi = __uint_as_float(g_maxiou[gi]);
        float na = g_al[idx] * mi * __fdividef(1.0f, ma + EPSA);
        // cls correction: replace the negative-assumed label term with the true one
        float x  = cls[(size_t)idx*Cc + label];
        float em = __expf(-fabsf(x));
        float t  = 1.0f + em;
        float sp = fmaxf(x, 0.0f) + __logf(t);
        float sg = ((x >= 0.0f) ? 1.0f : em) * __fdividef(1.0f, t);
        dC = (double)((sp - x*na)*na - sp*0.75f*sg*sg);
        // box loss
        float4 p0 = g_dec[2*idx], p1 = g_dec[2*idx+1];
        float4 q0 = g_gt[3*gi], q1 = g_gt[3*gi+1], q2 = g_gt[3*gi+2];
        float hd = probiou_hd(p0.x, p0.y, p0.z, p0.w, p1.x, p1.y,
                              q0.x, q0.y, q0.z, q0.w, q1.x, q1.y);
        dB = (double)(hd * na);
        // angle CE
        float tA = q2.z / ANGLE_SCALE_F;
        tA = fminf(fmaxf(tA, 0.0f), 89.99f);
        int li = (int)tA;
        int ri = min(li + 1, 90);
        float lw = (float)ri - tA;
        float rw = 1.0f - lw;
        float lse = p1.z;
        const float* ra = raw + (size_t)idx*ABp;
        dA = (double)((lse - ra[li])*lw + (lse - ra[ri])*rw);
        dS = (double)na;
        dN = 1.0;
    }
    double vals[5] = {dC, dB, dA, dS, dN};
    #pragma unroll
    for (int k = 0; k < 5; k++){
        double v = block_red(vals[k]);
        if (tid == 0) g_ppart[blockIdx.x*5 + k] = v;
    }
    __threadfence();
    __shared__ int slast;
    if (tid == 0) slast = (atomicAdd(&g_done, 1) == POSBLK - 1) ? 1 : 0;
    __syncthreads();
    if (!slast) return;
    __threadfence();
    // final deterministic reduce
    double accC = 0.0;
    for (int j = tid; j < NEGP; j += 256) accC += g_negpart[j];
    double acc[5] = {0, 0, 0, 0, 0};
    for (int j = tid; j < POSBLK; j += 256){
        #pragma unroll
        for (int k = 0; k < 5; k++) acc[k] += g_ppart[j*5 + k];
    }
    __shared__ double fin[6];
    double v = block_red(accC);
    if (tid == 0) fin[0] = v;
    #pragma unroll
    for (int k = 0; k < 5; k++){
        v = block_red(acc[k]);
        if (tid == 0) fin[1 + k] = v;
    }
    __syncthreads();
    if (tid == 0){
        double ss   = fmax(fin[4], 1.0);             // score_sum
        double lcls = (fin[0] + fin[1]) / ss;        // neg sum + pos corrections
        double lbox = fin[2] / ss;
        double np_  = fmax(fin[5], 1.0);
        double lang = fin[3] / np_;
        out[0] = (float)(lcls + 2.5*lbox + 0.05*lang);
        out[1] = (float)lcls;
        out[2] = (float)lbox;
        out[3] = (float)lang;
        // reset counters for next graph replay (deterministic)
        g_nitems = 0; g_npos = 0; g_done = 0; g_sync = 0;
    }
}

extern "C" void kernel_launch(void* const* d_in, const int* in_sizes, int n_in,
                              void* d_out, int out_size){
    const float* cls = (const float*)d_in[0];
    const float* reg = (const float*)d_in[1];
    const float* raw = (const float*)d_in[2];
    const int*   gtl = (const int*)  d_in[3];
    const float* gtb = (const float*)d_in[4];
    const float* vm  = (const float*)d_in[5];

    k_prep<<<PREPBLK, 256>>>(cls, gtb, vm);
    k_work<<<1024, 256>>>(cls, raw, reg, gtl);
    k_rank<<<512, 256>>>();
    k_post<<<POSBLK, 256>>>(cls, raw, gtl, (float*)d_out);
}